// round 13
// baseline (speedup 1.0000x reference)
#include <cuda_runtime.h>
#include <math.h>
#include <stdint.h>

// Shapes
#define NB 8
#define NS 4096
#define ND 2048
#define NH 16
#define NDK 128
#define SCALE 0.08838834764831845f   // 1/sqrt(128)

typedef unsigned long long u64;

__device__ __forceinline__ void ffma2(u64& d, u64 a, u64 b) {
    asm("fma.rn.f32x2 %0, %1, %2, %0;" : "+l"(d) : "l"(a), "l"(b));
}
__device__ __forceinline__ u64 pack2(float x, float y) {
    u64 r; asm("mov.b64 %0, {%1, %2};" : "=l"(r) : "f"(x), "f"(y)); return r;
}
__device__ __forceinline__ float2 unpack2(u64 v) {
    float2 r; asm("mov.b64 {%0, %1}, %2;" : "=f"(r.x), "=f"(r.y) : "l"(v)); return r;
}
// pack (x0,x1) -> bf16x2, x0 in LOW half
__device__ __forceinline__ uint32_t bf16x2_of(float x0, float x1) {
    uint32_t r; asm("cvt.rn.bf16x2.f32 %0, %2, %1;" : "=r"(r) : "f"(x0), "f"(x1)); return r;
}
// split a float2 into bf16x2 hi and bf16x2 lo (residual)
__device__ __forceinline__ void cvt_split(float2 f, uint32_t& hi, uint32_t& lo) {
    hi = bf16x2_of(f.x, f.y);
    float rx = f.x - __uint_as_float(hi << 16);
    float ry = f.y - __uint_as_float(hi & 0xffff0000u);
    lo = bf16x2_of(rx, ry);
}
// warp-level bf16 MMA, m16n8k16, fp32 accumulate (baseline PTX, sm_80+)
__device__ __forceinline__ void mma_bf16(float& d0, float& d1, float& d2, float& d3,
                                         uint32_t a0, uint32_t a1, uint32_t a2, uint32_t a3,
                                         uint32_t b0, uint32_t b1) {
    asm("mma.sync.aligned.m16n8k16.row.col.f32.bf16.bf16.f32 "
        "{%0,%1,%2,%3}, {%4,%5,%6,%7}, {%8,%9}, {%0,%1,%2,%3};"
        : "+f"(d0), "+f"(d1), "+f"(d2), "+f"(d3)
        : "r"(a0), "r"(a1), "r"(a2), "r"(a3), "r"(b0), "r"(b1));
}

// -------- device scratch (no allocations allowed) --------
__device__ __align__(16) float g_qbp[16 * NB * ND];
__device__ __align__(16) float g_qb[NB * ND];                 // [b][h*128+d]
__device__ __align__(16) float g_A[NB * NH * ND];             // A[b][h][e]
// packed bf16 B-fragments of g_A: [b][h][chunk(128)][slot(8)]
// slot 2t = k-pair t, slot 2t+1 = k-pair t+4 (chunk = 16 consecutive e)
__device__ __align__(16) uint32_t g_Bh[NB * NH * 128 * 8];
__device__ __align__(16) uint32_t g_Bl[NB * NH * 128 * 8];
__device__ __align__(16) float g_sp[4][NS * NB * NH];         // K-split score partials
__device__ __align__(16) float g_scores[NS * NB * NH];
__device__ float g_m[NB * NH];
__device__ float g_linv[NB * NH];
__device__ __align__(16) float g_upart[32 * NB * NH * ND];    // [jc(32)][b][h][e]
__device__ __align__(16) float g_xpart[16 * NB * ND];
__device__ __align__(16) float g_x[NB * ND];
__device__ __align__(16) float g_opart[16 * NB * ND];

// ---------------- K1: qb partials: (query @ Wq), g-split 16, MLP 8 ----------------
__global__ __launch_bounds__(256) void k_qbp(const float* __restrict__ query,
                                             const float* __restrict__ Wq) {
    int tid = threadIdx.x;
    int c   = blockIdx.x * 256 + tid;
    int g0  = blockIdx.y * 128;
    __shared__ float qs[8][128];
    for (int idx = tid; idx < 1024; idx += 256)
        qs[idx >> 7][idx & 127] = query[(idx >> 7) * ND + g0 + (idx & 127)];
    __syncthreads();
    float acc[8] = {0.f,0.f,0.f,0.f,0.f,0.f,0.f,0.f};
    for (int g = 0; g < 128; g += 8) {
        float w[8];
#pragma unroll
        for (int k2 = 0; k2 < 8; k2++) w[k2] = Wq[(g0 + g + k2) * ND + c];
#pragma unroll
        for (int k2 = 0; k2 < 8; k2++)
#pragma unroll
            for (int b = 0; b < 8; b++) acc[b] = fmaf(w[k2], qs[b][g + k2], acc[b]);
    }
#pragma unroll
    for (int b = 0; b < 8; b++) g_qbp[(blockIdx.y * 8 + b) * ND + c] = acc[b];
}

__global__ void k_qb(const float* __restrict__ q_bias) {
    int i = blockIdx.x * 256 + threadIdx.x;
    int c = i & (ND - 1);
    int b = i >> 11;
    float s = q_bias[c];
#pragma unroll
    for (int gc = 0; gc < 16; gc++) s += g_qbp[(gc * 8 + b) * ND + c];
    g_qb[i] = s;
}

// ---------------- K2: A[b][h][e] = Wk.qb, plus bf16 hi/lo fragment packing ----------------
__global__ void k_A(const float* __restrict__ Wk) {
    int tid = threadIdx.x;           // 128
    int h   = blockIdx.y;
    int e0  = blockIdx.x * 128;
    __shared__ float qbs[8][128];
    __shared__ float wks[128][65];
    __shared__ float as2[8][128];
    for (int idx = tid; idx < 1024; idx += 128)
        qbs[idx >> 7][idx & 127] = g_qb[(idx >> 7) * ND + h * NDK + (idx & 127)];
    float acc[8] = {0.f,0.f,0.f,0.f,0.f,0.f,0.f,0.f};
    for (int st = 0; st < 2; st++) {
        __syncthreads();
        for (int idx = tid; idx < 128 * 64; idx += 128) {
            int r = idx >> 6, cc = idx & 63;
            wks[r][cc] = Wk[(e0 + r) * ND + h * NDK + st * 64 + cc];
        }
        __syncthreads();
#pragma unroll 8
        for (int d = 0; d < 64; d++) {
            float w = wks[tid][d];
#pragma unroll
            for (int b = 0; b < 8; b++) acc[b] = fmaf(w, qbs[b][st * 64 + d], acc[b]);
        }
    }
    int e = e0 + tid;
#pragma unroll
    for (int b = 0; b < 8; b++) {
        g_A[(b * NH + h) * ND + e] = acc[b];
        as2[b][tid] = acc[b];
    }
    __syncthreads();
    // pack bf16 hi/lo fragments: block covers 8 chunks (16 e each) for this h
#pragma unroll
    for (int it = 0; it < 4; it++) {
        int idx = tid + it * 128;            // 0..511 = b(8) x chunk(8) x slot(8)
        int bb = idx >> 6, c = (idx >> 3) & 7, s = idx & 7;
        int p = (s >> 1) + ((s & 1) << 2);   // slot->k-pair: 2t->t, 2t+1->t+4
        int ep = c * 16 + 2 * p;
        float2 f = make_float2(as2[bb][ep], as2[bb][ep + 1]);
        uint32_t hi, lo;
        cvt_split(f, hi, lo);
        int off = ((bb * NH + h) * 128 + blockIdx.x * 8 + c) * 8 + s;
        g_Bh[off] = hi;
        g_Bl[off] = lo;
    }
}

// ---------------- K4: score pass via mma.sync, K-split x4, prepacked B ----------------
// Warp = 16 j x 16 h over a 512-wide K quarter. Partials to g_sp[kc].
__global__ __launch_bounds__(256) void k_scores(const float* __restrict__ key) {
    const int b = blockIdx.y, kc = blockIdx.z;
    const int warp = threadIdx.x >> 5, lane = threadIdx.x & 31;
    const int g = lane >> 2, t = lane & 3;
    const int j0 = blockIdx.x * 128 + warp * 16;

    float d0[4] = {0.f, 0.f, 0.f, 0.f};
    float d1[4] = {0.f, 0.f, 0.f, 0.f};

    const float* arow0 = key + ((size_t)(j0 + g) * NB + b) * ND + kc * 512 + 2 * t;
    const float* arow8 = arow0 + (size_t)8 * NB * ND;
    const uint32_t* bh0 = g_Bh + ((size_t)(b * NH + g)     * 128 + kc * 32) * 8 + 2 * t;
    const uint32_t* bh1 = g_Bh + ((size_t)(b * NH + 8 + g) * 128 + kc * 32) * 8 + 2 * t;
    const uint32_t* bl0 = g_Bl + ((size_t)(b * NH + g)     * 128 + kc * 32) * 8 + 2 * t;
    const uint32_t* bl1 = g_Bl + ((size_t)(b * NH + 8 + g) * 128 + kc * 32) * 8 + 2 * t;

#pragma unroll 4
    for (int c = 0; c < 32; c++) {
        float2 fa0 = *(const float2*)(arow0 + c * 16);
        float2 fa1 = *(const float2*)(arow8 + c * 16);
        float2 fa2 = *(const float2*)(arow0 + c * 16 + 8);
        float2 fa3 = *(const float2*)(arow8 + c * 16 + 8);
        uint2 B0h = *(const uint2*)(bh0 + c * 8);   // .x = b0 (pair t), .y = b1 (pair t+4)
        uint2 B1h = *(const uint2*)(bh1 + c * 8);
        uint2 B0l = *(const uint2*)(bl0 + c * 8);
        uint2 B1l = *(const uint2*)(bl1 + c * 8);

        uint32_t ah[4], al[4];
        cvt_split(fa0, ah[0], al[0]);
        cvt_split(fa1, ah[1], al[1]);
        cvt_split(fa2, ah[2], al[2]);
        cvt_split(fa3, ah[3], al[3]);

        // n-tile 0 (h 0..7): hi*hi + hi*lo + lo*hi
        mma_bf16(d0[0], d0[1], d0[2], d0[3], ah[0], ah[1], ah[2], ah[3], B0h.x, B0h.y);
        mma_bf16(d0[0], d0[1], d0[2], d0[3], ah[0], ah[1], ah[2], ah[3], B0l.x, B0l.y);
        mma_bf16(d0[0], d0[1], d0[2], d0[3], al[0], al[1], al[2], al[3], B0h.x, B0h.y);
        // n-tile 1 (h 8..15)
        mma_bf16(d1[0], d1[1], d1[2], d1[3], ah[0], ah[1], ah[2], ah[3], B1h.x, B1h.y);
        mma_bf16(d1[0], d1[1], d1[2], d1[3], ah[0], ah[1], ah[2], ah[3], B1l.x, B1l.y);
        mma_bf16(d1[0], d1[1], d1[2], d1[3], al[0], al[1], al[2], al[3], B1h.x, B1h.y);
    }

    float* sp = g_sp[kc];
    const int jA = j0 + g, jB = j0 + g + 8;
    const int colA = jA * 128 + b * 16, colB = jB * 128 + b * 16;
    sp[colA + 2 * t]         = d0[0];
    sp[colA + 2 * t + 1]     = d0[1];
    sp[colB + 2 * t]         = d0[2];
    sp[colB + 2 * t + 1]     = d0[3];
    sp[colA + 8 + 2 * t]     = d1[0];
    sp[colA + 8 + 2 * t + 1] = d1[1];
    sp[colB + 8 + 2 * t]     = d1[2];
    sp[colB + 8 + 2 * t + 1] = d1[3];
}

// ---------------- K3: g_scores = SCALE * (sum_kc sp[kc] + qb.key_pos) ----------------
__global__ __launch_bounds__(256) void k_pos(const float* __restrict__ key_pos) {
    const int warp = threadIdx.x >> 5, lane = threadIdx.x & 31;
    const int h  = blockIdx.y * 8 + warp;
    const int j0 = blockIdx.x * 4;

    u64 qb[8][2];
#pragma unroll
    for (int bb = 0; bb < 8; bb++) {
        ulonglong2 q = *(const ulonglong2*)&g_qb[bb * ND + h * NDK + lane * 4];
        qb[bb][0] = q.x; qb[bb][1] = q.y;
    }
    u64 acc[4][8];
#pragma unroll
    for (int jj = 0; jj < 4; jj++)
#pragma unroll
        for (int bb = 0; bb < 8; bb++) acc[jj][bb] = 0ull;

#pragma unroll
    for (int jj = 0; jj < 4; jj++) {
        ulonglong2 kp = *(const ulonglong2*)&key_pos[((size_t)(j0 + jj) * NH + h) * NDK + lane * 4];
#pragma unroll
        for (int bb = 0; bb < 8; bb++) {
            ffma2(acc[jj][bb], qb[bb][0], kp.x);
            ffma2(acc[jj][bb], qb[bb][1], kp.y);
        }
    }
    float v[32];
#pragma unroll
    for (int jj = 0; jj < 4; jj++)
#pragma unroll
        for (int bb = 0; bb < 8; bb++) {
            float2 p = unpack2(acc[jj][bb]);
            v[jj * 8 + bb] = p.x + p.y;
        }
    int n = 32;
#pragma unroll
    for (int half = 16; half >= 1; half >>= 1) {
        int m = n >> 1;
        bool upper = (lane & half) != 0;
#pragma unroll
        for (int i = 0; i < 16; i++) {
            if (i >= m) break;
            float send = upper ? v[i] : v[i + m];
            float recv = __shfl_xor_sync(0xffffffffu, send, half);
            v[i] = (upper ? v[i + m] : v[i]) + recv;
        }
        n = m;
    }
    int jj = lane >> 3, bb = lane & 7;
    int gi = (j0 + jj) * 128 + bb * 16 + h;
    float s = g_sp[0][gi] + g_sp[1][gi] + g_sp[2][gi] + g_sp[3][gi] + v[0];
    g_scores[gi] = s * SCALE;
}

// ---------------- K5: softmax stats per (b,h) ----------------
__global__ void k_softmax() {
    int bh = blockIdx.x;
    int tid = threadIdx.x;
    __shared__ float red[256];
    float mx = -1e30f;
    for (int j = tid; j < NS; j += 256)
        mx = fmaxf(mx, g_scores[j * (NB * NH) + bh]);
    red[tid] = mx; __syncthreads();
    for (int s = 128; s; s >>= 1) { if (tid < s) red[tid] = fmaxf(red[tid], red[tid + s]); __syncthreads(); }
    float m = red[0]; __syncthreads();
    float sum = 0.f;
    for (int j = tid; j < NS; j += 256)
        sum += __expf(g_scores[j * (NB * NH) + bh] - m);
    red[tid] = sum; __syncthreads();
    for (int s = 128; s; s >>= 1) { if (tid < s) red[tid] += red[tid + s]; __syncthreads(); }
    if (tid == 0) { g_m[bh] = m; g_linv[bh] = 1.0f / red[0]; }
}

// ---------------- K6: value pass — float4, 4 e-cols/thread ----------------
__global__ __launch_bounds__(256) void k_value(const float* __restrict__ value) {
    const int tid = threadIdx.x;
    const int b = blockIdx.y, jc = blockIdx.z;
    const int e = blockIdx.x * 1024 + tid * 4;
    const int j0 = jc * 128;
    __shared__ __align__(16) u64 ws2[128 * 16];
    __shared__ float ms[16], ls[16];
    if (tid < 16) { ms[tid] = g_m[b * 16 + tid]; ls[tid] = g_linv[b * 16 + tid]; }
    __syncthreads();
    for (int idx = tid; idx < 2048; idx += 256) {
        int jl = idx >> 4, h = idx & 15;
        float w = __expf(g_scores[(j0 + jl) * 128 + b * 16 + h] - ms[h]) * ls[h];
        ws2[idx] = pack2(w, w);
    }
    __syncthreads();

    u64 acc[16][2];
#pragma unroll
    for (int h = 0; h < 16; h++) { acc[h][0] = 0ull; acc[h][1] = 0ull; }

    const float* vp = value + ((size_t)j0 * NB + b) * ND + e;
#pragma unroll 4
    for (int jl = 0; jl < 128; jl++) {
        ulonglong2 v2 = *(const ulonglong2*)(vp + (size_t)jl * (NB * ND));
        const ulonglong2* wr = (const ulonglong2*)(ws2 + jl * 16);
#pragma unroll
        for (int h2 = 0; h2 < 8; h2++) {
            ulonglong2 wp = wr[h2];
            ffma2(acc[2 * h2    ][0], wp.x, v2.x);
            ffma2(acc[2 * h2    ][1], wp.x, v2.y);
            ffma2(acc[2 * h2 + 1][0], wp.y, v2.x);
            ffma2(acc[2 * h2 + 1][1], wp.y, v2.y);
        }
    }
    int rb = (jc * 8 + b) * 16;
#pragma unroll
    for (int h = 0; h < 16; h++) {
        ulonglong2 o; o.x = acc[h][0]; o.y = acc[h][1];
        *(ulonglong2*)&g_upart[(size_t)(rb + h) * ND + e] = o;
    }
}

// ---------------- K7: x partials = u @ Wv (per head), e-split 16 ----------------
__global__ __launch_bounds__(128) void k_projv(const float* __restrict__ Wv) {
    int tid = threadIdx.x;   // 128 (= d)
    int h = blockIdx.y;
    int e0 = blockIdx.x * 128;
    __shared__ float us[8][128];
    for (int idx = tid; idx < 1024; idx += 128) {
        int bb = idx >> 7, el = idx & 127;
        float s = 0.f;
#pragma unroll
        for (int jc = 0; jc < 32; jc++)
            s += g_upart[(size_t)((jc * 8 + bb) * 16 + h) * ND + e0 + el];
        us[bb][el] = s;
    }
    __syncthreads();
    float acc[8] = {0.f,0.f,0.f,0.f,0.f,0.f,0.f,0.f};
    for (int el = 0; el < 128; el += 8) {
        float w[8];
#pragma unroll
        for (int k2 = 0; k2 < 8; k2++)
            w[k2] = Wv[(e0 + el + k2) * ND + h * NDK + tid];
#pragma unroll
        for (int k2 = 0; k2 < 8; k2++)
#pragma unroll
            for (int bb = 0; bb < 8; bb++) acc[bb] = fmaf(w[k2], us[bb][el + k2], acc[bb]);
    }
#pragma unroll
    for (int bb = 0; bb < 8; bb++)
        g_xpart[(blockIdx.x * 8 + bb) * ND + h * NDK + tid] = acc[bb];
}

__global__ void k_xred(const float* __restrict__ bv) {
    int i = blockIdx.x * 256 + threadIdx.x;
    int c = i & (ND - 1), b = i >> 11;
    float s = bv[c];
#pragma unroll
    for (int ec = 0; ec < 16; ec++) s += g_xpart[(ec * 8 + b) * ND + c];
    g_x[i] = s;
}

// ---------------- K8: out partials = x @ Wo, g-split 16, MLP 8 ----------------
__global__ __launch_bounds__(256) void k_out(const float* __restrict__ Wo) {
    int tid = threadIdx.x;
    int f = blockIdx.x * 256 + tid;
    int g0 = blockIdx.y * 128;
    __shared__ float xs[8][128];
    for (int idx = tid; idx < 1024; idx += 256)
        xs[idx >> 7][idx & 127] = g_x[(idx >> 7) * ND + g0 + (idx & 127)];
    __syncthreads();
    float acc[8] = {0.f,0.f,0.f,0.f,0.f,0.f,0.f,0.f};
    for (int g = 0; g < 128; g += 8) {
        float w[8];
#pragma unroll
        for (int k2 = 0; k2 < 8; k2++) w[k2] = Wo[(g0 + g + k2) * ND + f];
#pragma unroll
        for (int k2 = 0; k2 < 8; k2++)
#pragma unroll
            for (int b = 0; b < 8; b++) acc[b] = fmaf(w[k2], xs[b][g + k2], acc[b]);
    }
#pragma unroll
    for (int b = 0; b < 8; b++) g_opart[(blockIdx.y * 8 + b) * ND + f] = acc[b];
}

__global__ void k_ored(const float* __restrict__ bo, float* __restrict__ out) {
    int i = blockIdx.x * 256 + threadIdx.x;
    int c = i & (ND - 1), b = i >> 11;
    float s = bo[c];
#pragma unroll
    for (int gc = 0; gc < 16; gc++) s += g_opart[(gc * 8 + b) * ND + c];
    out[i] = s;
}

extern "C" void kernel_launch(void* const* d_in, const int* in_sizes, int n_in,
                              void* d_out, int out_size) {
    const float* query   = (const float*)d_in[0];
    const float* key     = (const float*)d_in[1];
    const float* value   = (const float*)d_in[2];
    const float* Wq      = (const float*)d_in[3];
    const float* Wk      = (const float*)d_in[4];
    const float* Wv      = (const float*)d_in[5];
    const float* bv      = (const float*)d_in[6];
    const float* Wo      = (const float*)d_in[7];
    const float* bo      = (const float*)d_in[8];
    const float* key_pos = (const float*)d_in[9];
    const float* q_bias  = (const float*)d_in[10];
    float* out = (float*)d_out;

    // k_scores kept at launch idx 3 so the profiler's fixed slot lands on it.
    k_qbp    <<<dim3(8, 16),     256>>>(query, Wq);
    k_qb     <<<64,              256>>>(q_bias);
    k_A      <<<dim3(16, 16),    128>>>(Wk);
    k_scores <<<dim3(32, 8, 4),  256>>>(key);
    k_pos    <<<dim3(1024, 2),   256>>>(key_pos);
    k_softmax<<<128,             256>>>();
    k_value  <<<dim3(2, 8, 32),  256>>>(value);
    k_projv  <<<dim3(16, 16),    128>>>(Wv);
    k_xred   <<<64,              256>>>(bv);
    k_out    <<<dim3(8, 16),     256>>>(Wo);
    k_ored   <<<64,              256>>>(bo, out);
}

// round 14
// speedup vs baseline: 1.2827x; 1.2827x over previous
#include <cuda_runtime.h>
#include <math.h>
#include <stdint.h>

// Shapes
#define NB 8
#define NS 4096
#define ND 2048
#define NH 16
#define NDK 128
#define SCALE 0.08838834764831845f   // 1/sqrt(128)

typedef unsigned long long u64;

__device__ __forceinline__ void ffma2(u64& d, u64 a, u64 b) {
    asm("fma.rn.f32x2 %0, %1, %2, %0;" : "+l"(d) : "l"(a), "l"(b));
}
__device__ __forceinline__ u64 pack2(float x, float y) {
    u64 r; asm("mov.b64 %0, {%1, %2};" : "=l"(r) : "f"(x), "f"(y)); return r;
}
__device__ __forceinline__ float2 unpack2(u64 v) {
    float2 r; asm("mov.b64 {%0, %1}, %2;" : "=f"(r.x), "=f"(r.y) : "l"(v)); return r;
}
// pack (x0,x1) -> bf16x2, x0 in LOW half
__device__ __forceinline__ uint32_t bf16x2_of(float x0, float x1) {
    uint32_t r; asm("cvt.rn.bf16x2.f32 %0, %2, %1;" : "=r"(r) : "f"(x0), "f"(x1)); return r;
}
// split a float2 into bf16x2 hi and bf16x2 lo (residual)
__device__ __forceinline__ void cvt_split(float2 f, uint32_t& hi, uint32_t& lo) {
    hi = bf16x2_of(f.x, f.y);
    float rx = f.x - __uint_as_float(hi << 16);
    float ry = f.y - __uint_as_float(hi & 0xffff0000u);
    lo = bf16x2_of(rx, ry);
}
// warp-level bf16 MMA, m16n8k16, fp32 accumulate (baseline PTX, sm_80+)
__device__ __forceinline__ void mma_bf16(float& d0, float& d1, float& d2, float& d3,
                                         uint32_t a0, uint32_t a1, uint32_t a2, uint32_t a3,
                                         uint32_t b0, uint32_t b1) {
    asm("mma.sync.aligned.m16n8k16.row.col.f32.bf16.bf16.f32 "
        "{%0,%1,%2,%3}, {%4,%5,%6,%7}, {%8,%9}, {%0,%1,%2,%3};"
        : "+f"(d0), "+f"(d1), "+f"(d2), "+f"(d3)
        : "r"(a0), "r"(a1), "r"(a2), "r"(a3), "r"(b0), "r"(b1));
}

// -------- device scratch (no allocations allowed) --------
__device__ __align__(16) float g_qbp[16 * NB * ND];
__device__ __align__(16) float g_qb[NB * ND];                 // [b][h*128+d]
__device__ __align__(16) float g_A[NB * NH * ND];             // A[b][h][e]
// packed bf16 B-fragments of g_A: [b][h][chunk(128)][slot(8)]
// slot 2t = k-pair t, slot 2t+1 = k-pair t+4 (chunk = 16 consecutive e)
__device__ __align__(16) uint32_t g_Bh[NB * NH * 128 * 8];
__device__ __align__(16) uint32_t g_Bl[NB * NH * 128 * 8];
__device__ __align__(16) float g_sp[4][NS * NB * NH];         // K-split score partials
__device__ __align__(16) float g_scores[NS * NB * NH];
__device__ float g_m[NB * NH];
__device__ float g_linv[NB * NH];
__device__ __align__(16) float g_upart[32 * NB * NH * ND];    // [jc(32)][b][h][e]
__device__ __align__(16) float g_xpart[16 * NB * ND];
__device__ __align__(16) float g_x[NB * ND];
__device__ __align__(16) float g_opart[16 * NB * ND];

// ---------------- K1: qb partials: (query @ Wq), g-split 16, MLP 8 ----------------
__global__ __launch_bounds__(256) void k_qbp(const float* __restrict__ query,
                                             const float* __restrict__ Wq) {
    int tid = threadIdx.x;
    int c   = blockIdx.x * 256 + tid;
    int g0  = blockIdx.y * 128;
    __shared__ float qs[8][128];
    for (int idx = tid; idx < 1024; idx += 256)
        qs[idx >> 7][idx & 127] = query[(idx >> 7) * ND + g0 + (idx & 127)];
    __syncthreads();
    float acc[8] = {0.f,0.f,0.f,0.f,0.f,0.f,0.f,0.f};
    for (int g = 0; g < 128; g += 8) {
        float w[8];
#pragma unroll
        for (int k2 = 0; k2 < 8; k2++) w[k2] = Wq[(g0 + g + k2) * ND + c];
#pragma unroll
        for (int k2 = 0; k2 < 8; k2++)
#pragma unroll
            for (int b = 0; b < 8; b++) acc[b] = fmaf(w[k2], qs[b][g + k2], acc[b]);
    }
#pragma unroll
    for (int b = 0; b < 8; b++) g_qbp[(blockIdx.y * 8 + b) * ND + c] = acc[b];
}

__global__ void k_qb(const float* __restrict__ q_bias) {
    int i = blockIdx.x * 256 + threadIdx.x;
    int c = i & (ND - 1);
    int b = i >> 11;
    float s = q_bias[c];
#pragma unroll
    for (int gc = 0; gc < 16; gc++) s += g_qbp[(gc * 8 + b) * ND + c];
    g_qb[i] = s;
}

// ---------------- K2: A[b][h][e] = Wk.qb, plus bf16 hi/lo fragment packing ----------------
__global__ void k_A(const float* __restrict__ Wk) {
    int tid = threadIdx.x;           // 128
    int h   = blockIdx.y;
    int e0  = blockIdx.x * 128;
    __shared__ float qbs[8][128];
    __shared__ float wks[128][65];
    __shared__ float as2[8][128];
    for (int idx = tid; idx < 1024; idx += 128)
        qbs[idx >> 7][idx & 127] = g_qb[(idx >> 7) * ND + h * NDK + (idx & 127)];
    float acc[8] = {0.f,0.f,0.f,0.f,0.f,0.f,0.f,0.f};
    for (int st = 0; st < 2; st++) {
        __syncthreads();
        for (int idx = tid; idx < 128 * 64; idx += 128) {
            int r = idx >> 6, cc = idx & 63;
            wks[r][cc] = Wk[(e0 + r) * ND + h * NDK + st * 64 + cc];
        }
        __syncthreads();
#pragma unroll 8
        for (int d = 0; d < 64; d++) {
            float w = wks[tid][d];
#pragma unroll
            for (int b = 0; b < 8; b++) acc[b] = fmaf(w, qbs[b][st * 64 + d], acc[b]);
        }
    }
    int e = e0 + tid;
#pragma unroll
    for (int b = 0; b < 8; b++) {
        g_A[(b * NH + h) * ND + e] = acc[b];
        as2[b][tid] = acc[b];
    }
    __syncthreads();
    // pack bf16 hi/lo fragments: block covers 8 chunks (16 e each) for this h
#pragma unroll
    for (int it = 0; it < 4; it++) {
        int idx = tid + it * 128;            // 0..511 = b(8) x chunk(8) x slot(8)
        int bb = idx >> 6, c = (idx >> 3) & 7, s = idx & 7;
        int p = (s >> 1) + ((s & 1) << 2);   // slot->k-pair: 2t->t, 2t+1->t+4
        int ep = c * 16 + 2 * p;
        float2 f = make_float2(as2[bb][ep], as2[bb][ep + 1]);
        uint32_t hi, lo;
        cvt_split(f, hi, lo);
        int off = ((bb * NH + h) * 128 + blockIdx.x * 8 + c) * 8 + s;
        g_Bh[off] = hi;
        g_Bl[off] = lo;
    }
}

// ---------------- K4: score pass — mma.sync + smem-staged A, double-buffered ----------------
// CTA = 8 warps x 16 j = 128 j rows, one 512-wide K quarter (kc). Per 16-e chunk:
// coalesced fp32 load -> bf16 hi/lo split -> smem tile (pad 12: conflict-free LDS).
__global__ __launch_bounds__(256) void k_scores(const float* __restrict__ key) {
    const int b = blockIdx.y, kc = blockIdx.z;
    const int tid = threadIdx.x;
    const int warp = tid >> 5, lane = tid & 31;
    const int g = lane >> 2, t = lane & 3;

    __shared__ __align__(16) uint32_t Sh[2][128][12];   // 12 KB (pad 12 -> no LDS conflicts)
    __shared__ __align__(16) uint32_t Sl[2][128][12];   // 12 KB

    const int srow = tid >> 1, shalf = tid & 1;
    const float* src = key + ((size_t)(blockIdx.x * 128 + srow) * NB + b) * ND
                           + kc * 512 + shalf * 8;

    float4 r0, r1;
    auto LD = [&](int c) {
        r0 = *(const float4*)(src + c * 16);
        r1 = *(const float4*)(src + c * 16 + 4);
    };
    auto ST = [&](int buf) {
        uint32_t h0,l0,h1,l1,h2,l2,h3,l3;
        cvt_split(make_float2(r0.x, r0.y), h0, l0);
        cvt_split(make_float2(r0.z, r0.w), h1, l1);
        cvt_split(make_float2(r1.x, r1.y), h2, l2);
        cvt_split(make_float2(r1.z, r1.w), h3, l3);
        *(uint4*)&Sh[buf][srow][shalf * 4] = make_uint4(h0, h1, h2, h3);
        *(uint4*)&Sl[buf][srow][shalf * 4] = make_uint4(l0, l1, l2, l3);
    };

    float d0[4] = {0.f, 0.f, 0.f, 0.f};
    float d1[4] = {0.f, 0.f, 0.f, 0.f};

    const uint32_t* bh0 = g_Bh + ((size_t)(b * NH + g)     * 128 + kc * 32) * 8 + 2 * t;
    const uint32_t* bh1 = g_Bh + ((size_t)(b * NH + 8 + g) * 128 + kc * 32) * 8 + 2 * t;
    const uint32_t* bl0 = g_Bl + ((size_t)(b * NH + g)     * 128 + kc * 32) * 8 + 2 * t;
    const uint32_t* bl1 = g_Bl + ((size_t)(b * NH + 8 + g) * 128 + kc * 32) * 8 + 2 * t;

    const int ar = warp * 16 + g;     // A-frag rows (and ar+8)

    LD(0); ST(0);
    LD(1);
    __syncthreads();

#pragma unroll 1
    for (int c = 0; c < 32; c++) {
        const int buf = c & 1;
        // A fragments from smem (conflict-free LDS.32 with pad 12)
        uint32_t ah0 = Sh[buf][ar][t],       ah1 = Sh[buf][ar + 8][t];
        uint32_t ah2 = Sh[buf][ar][t + 4],   ah3 = Sh[buf][ar + 8][t + 4];
        uint32_t al0 = Sl[buf][ar][t],       al1 = Sl[buf][ar + 8][t];
        uint32_t al2 = Sl[buf][ar][t + 4],   al3 = Sl[buf][ar + 8][t + 4];
        uint2 B0h = *(const uint2*)(bh0 + c * 8);
        uint2 B1h = *(const uint2*)(bh1 + c * 8);
        uint2 B0l = *(const uint2*)(bl0 + c * 8);
        uint2 B1l = *(const uint2*)(bl1 + c * 8);

        // n-tile 0 (h 0..7): hi*hi + hi*lo + lo*hi
        mma_bf16(d0[0], d0[1], d0[2], d0[3], ah0, ah1, ah2, ah3, B0h.x, B0h.y);
        mma_bf16(d0[0], d0[1], d0[2], d0[3], ah0, ah1, ah2, ah3, B0l.x, B0l.y);
        mma_bf16(d0[0], d0[1], d0[2], d0[3], al0, al1, al2, al3, B0h.x, B0h.y);
        // n-tile 1 (h 8..15)
        mma_bf16(d1[0], d1[1], d1[2], d1[3], ah0, ah1, ah2, ah3, B1h.x, B1h.y);
        mma_bf16(d1[0], d1[1], d1[2], d1[3], ah0, ah1, ah2, ah3, B1l.x, B1l.y);
        mma_bf16(d1[0], d1[1], d1[2], d1[3], al0, al1, al2, al3, B1h.x, B1h.y);

        if (c + 1 < 32) ST(buf ^ 1);      // stage chunk c+1 into the other buffer
        if (c + 2 < 32) LD(c + 2);        // prefetch chunk c+2 into registers
        __syncthreads();
    }

    float* sp = g_sp[kc];
    const int j0 = blockIdx.x * 128 + warp * 16;
    const int jA = j0 + g, jB = j0 + g + 8;
    const int colA = jA * 128 + b * 16, colB = jB * 128 + b * 16;
    sp[colA + 2 * t]         = d0[0];
    sp[colA + 2 * t + 1]     = d0[1];
    sp[colB + 2 * t]         = d0[2];
    sp[colB + 2 * t + 1]     = d0[3];
    sp[colA + 8 + 2 * t]     = d1[0];
    sp[colA + 8 + 2 * t + 1] = d1[1];
    sp[colB + 8 + 2 * t]     = d1[2];
    sp[colB + 8 + 2 * t + 1] = d1[3];
}

// ---------------- K3: g_scores = SCALE * (sum_kc sp[kc] + qb.key_pos) ----------------
__global__ __launch_bounds__(256) void k_pos(const float* __restrict__ key_pos) {
    const int warp = threadIdx.x >> 5, lane = threadIdx.x & 31;
    const int h  = blockIdx.y * 8 + warp;
    const int j0 = blockIdx.x * 4;

    u64 qb[8][2];
#pragma unroll
    for (int bb = 0; bb < 8; bb++) {
        ulonglong2 q = *(const ulonglong2*)&g_qb[bb * ND + h * NDK + lane * 4];
        qb[bb][0] = q.x; qb[bb][1] = q.y;
    }
    u64 acc[4][8];
#pragma unroll
    for (int jj = 0; jj < 4; jj++)
#pragma unroll
        for (int bb = 0; bb < 8; bb++) acc[jj][bb] = 0ull;

#pragma unroll
    for (int jj = 0; jj < 4; jj++) {
        ulonglong2 kp = *(const ulonglong2*)&key_pos[((size_t)(j0 + jj) * NH + h) * NDK + lane * 4];
#pragma unroll
        for (int bb = 0; bb < 8; bb++) {
            ffma2(acc[jj][bb], qb[bb][0], kp.x);
            ffma2(acc[jj][bb], qb[bb][1], kp.y);
        }
    }
    float v[32];
#pragma unroll
    for (int jj = 0; jj < 4; jj++)
#pragma unroll
        for (int bb = 0; bb < 8; bb++) {
            float2 p = unpack2(acc[jj][bb]);
            v[jj * 8 + bb] = p.x + p.y;
        }
    int n = 32;
#pragma unroll
    for (int half = 16; half >= 1; half >>= 1) {
        int m = n >> 1;
        bool upper = (lane & half) != 0;
#pragma unroll
        for (int i = 0; i < 16; i++) {
            if (i >= m) break;
            float send = upper ? v[i] : v[i + m];
            float recv = __shfl_xor_sync(0xffffffffu, send, half);
            v[i] = (upper ? v[i + m] : v[i]) + recv;
        }
        n = m;
    }
    int jj = lane >> 3, bb = lane & 7;
    int gi = (j0 + jj) * 128 + bb * 16 + h;
    float s = g_sp[0][gi] + g_sp[1][gi] + g_sp[2][gi] + g_sp[3][gi] + v[0];
    g_scores[gi] = s * SCALE;
}

// ---------------- K5: softmax stats per (b,h) ----------------
__global__ void k_softmax() {
    int bh = blockIdx.x;
    int tid = threadIdx.x;
    __shared__ float red[256];
    float mx = -1e30f;
    for (int j = tid; j < NS; j += 256)
        mx = fmaxf(mx, g_scores[j * (NB * NH) + bh]);
    red[tid] = mx; __syncthreads();
    for (int s = 128; s; s >>= 1) { if (tid < s) red[tid] = fmaxf(red[tid], red[tid + s]); __syncthreads(); }
    float m = red[0]; __syncthreads();
    float sum = 0.f;
    for (int j = tid; j < NS; j += 256)
        sum += __expf(g_scores[j * (NB * NH) + bh] - m);
    red[tid] = sum; __syncthreads();
    for (int s = 128; s; s >>= 1) { if (tid < s) red[tid] += red[tid + s]; __syncthreads(); }
    if (tid == 0) { g_m[bh] = m; g_linv[bh] = 1.0f / red[0]; }
}

// ---------------- K6: value pass — float4, 4 e-cols/thread ----------------
__global__ __launch_bounds__(256) void k_value(const float* __restrict__ value) {
    const int tid = threadIdx.x;
    const int b = blockIdx.y, jc = blockIdx.z;
    const int e = blockIdx.x * 1024 + tid * 4;
    const int j0 = jc * 128;
    __shared__ __align__(16) u64 ws2[128 * 16];
    __shared__ float ms[16], ls[16];
    if (tid < 16) { ms[tid] = g_m[b * 16 + tid]; ls[tid] = g_linv[b * 16 + tid]; }
    __syncthreads();
    for (int idx = tid; idx < 2048; idx += 256) {
        int jl = idx >> 4, h = idx & 15;
        float w = __expf(g_scores[(j0 + jl) * 128 + b * 16 + h] - ms[h]) * ls[h];
        ws2[idx] = pack2(w, w);
    }
    __syncthreads();

    u64 acc[16][2];
#pragma unroll
    for (int h = 0; h < 16; h++) { acc[h][0] = 0ull; acc[h][1] = 0ull; }

    const float* vp = value + ((size_t)j0 * NB + b) * ND + e;
#pragma unroll 4
    for (int jl = 0; jl < 128; jl++) {
        ulonglong2 v2 = *(const ulonglong2*)(vp + (size_t)jl * (NB * ND));
        const ulonglong2* wr = (const ulonglong2*)(ws2 + jl * 16);
#pragma unroll
        for (int h2 = 0; h2 < 8; h2++) {
            ulonglong2 wp = wr[h2];
            ffma2(acc[2 * h2    ][0], wp.x, v2.x);
            ffma2(acc[2 * h2    ][1], wp.x, v2.y);
            ffma2(acc[2 * h2 + 1][0], wp.y, v2.x);
            ffma2(acc[2 * h2 + 1][1], wp.y, v2.y);
        }
    }
    int rb = (jc * 8 + b) * 16;
#pragma unroll
    for (int h = 0; h < 16; h++) {
        ulonglong2 o; o.x = acc[h][0]; o.y = acc[h][1];
        *(ulonglong2*)&g_upart[(size_t)(rb + h) * ND + e] = o;
    }
}

// ---------------- K7: x partials = u @ Wv (per head), e-split 16 ----------------
__global__ __launch_bounds__(128) void k_projv(const float* __restrict__ Wv) {
    int tid = threadIdx.x;   // 128 (= d)
    int h = blockIdx.y;
    int e0 = blockIdx.x * 128;
    __shared__ float us[8][128];
    for (int idx = tid; idx < 1024; idx += 128) {
        int bb = idx >> 7, el = idx & 127;
        float s = 0.f;
#pragma unroll
        for (int jc = 0; jc < 32; jc++)
            s += g_upart[(size_t)((jc * 8 + bb) * 16 + h) * ND + e0 + el];
        us[bb][el] = s;
    }
    __syncthreads();
    float acc[8] = {0.f,0.f,0.f,0.f,0.f,0.f,0.f,0.f};
    for (int el = 0; el < 128; el += 8) {
        float w[8];
#pragma unroll
        for (int k2 = 0; k2 < 8; k2++)
            w[k2] = Wv[(e0 + el + k2) * ND + h * NDK + tid];
#pragma unroll
        for (int k2 = 0; k2 < 8; k2++)
#pragma unroll
            for (int bb = 0; bb < 8; bb++) acc[bb] = fmaf(w[k2], us[bb][el + k2], acc[bb]);
    }
#pragma unroll
    for (int bb = 0; bb < 8; bb++)
        g_xpart[(blockIdx.x * 8 + bb) * ND + h * NDK + tid] = acc[bb];
}

__global__ void k_xred(const float* __restrict__ bv) {
    int i = blockIdx.x * 256 + threadIdx.x;
    int c = i & (ND - 1), b = i >> 11;
    float s = bv[c];
#pragma unroll
    for (int ec = 0; ec < 16; ec++) s += g_xpart[(ec * 8 + b) * ND + c];
    g_x[i] = s;
}

// ---------------- K8: out partials = x @ Wo, g-split 16, MLP 8 ----------------
__global__ __launch_bounds__(256) void k_out(const float* __restrict__ Wo) {
    int tid = threadIdx.x;
    int f = blockIdx.x * 256 + tid;
    int g0 = blockIdx.y * 128;
    __shared__ float xs[8][128];
    for (int idx = tid; idx < 1024; idx += 256)
        xs[idx >> 7][idx & 127] = g_x[(idx >> 7) * ND + g0 + (idx & 127)];
    __syncthreads();
    float acc[8] = {0.f,0.f,0.f,0.f,0.f,0.f,0.f,0.f};
    for (int g = 0; g < 128; g += 8) {
        float w[8];
#pragma unroll
        for (int k2 = 0; k2 < 8; k2++) w[k2] = Wo[(g0 + g + k2) * ND + f];
#pragma unroll
        for (int k2 = 0; k2 < 8; k2++)
#pragma unroll
            for (int b = 0; b < 8; b++) acc[b] = fmaf(w[k2], xs[b][g + k2], acc[b]);
    }
#pragma unroll
    for (int b = 0; b < 8; b++) g_opart[(blockIdx.y * 8 + b) * ND + f] = acc[b];
}

__global__ void k_ored(const float* __restrict__ bo, float* __restrict__ out) {
    int i = blockIdx.x * 256 + threadIdx.x;
    int c = i & (ND - 1), b = i >> 11;
    float s = bo[c];
#pragma unroll
    for (int gc = 0; gc < 16; gc++) s += g_opart[(gc * 8 + b) * ND + c];
    out[i] = s;
}

extern "C" void kernel_launch(void* const* d_in, const int* in_sizes, int n_in,
                              void* d_out, int out_size) {
    const float* query   = (const float*)d_in[0];
    const float* key     = (const float*)d_in[1];
    const float* value   = (const float*)d_in[2];
    const float* Wq      = (const float*)d_in[3];
    const float* Wk      = (const float*)d_in[4];
    const float* Wv      = (const float*)d_in[5];
    const float* bv      = (const float*)d_in[6];
    const float* Wo      = (const float*)d_in[7];
    const float* bo      = (const float*)d_in[8];
    const float* key_pos = (const float*)d_in[9];
    const float* q_bias  = (const float*)d_in[10];
    float* out = (float*)d_out;

    // k_scores kept at launch idx 3 so the profiler's fixed slot lands on it.
    k_qbp    <<<dim3(8, 16),     256>>>(query, Wq);
    k_qb     <<<64,              256>>>(q_bias);
    k_A      <<<dim3(16, 16),    128>>>(Wk);
    k_scores <<<dim3(32, 8, 4),  256>>>(key);
    k_pos    <<<dim3(1024, 2),   256>>>(key_pos);
    k_softmax<<<128,             256>>>();
    k_value  <<<dim3(2, 8, 32),  256>>>(value);
    k_projv  <<<dim3(16, 16),    128>>>(Wv);
    k_xred   <<<64,              256>>>(bv);
    k_out    <<<dim3(8, 16),     256>>>(Wo);
    k_ored   <<<64,              256>>>(bo, out);
}

// round 15
// speedup vs baseline: 1.3055x; 1.0178x over previous
#include <cuda_runtime.h>
#include <math.h>
#include <stdint.h>

// Shapes
#define NB 8
#define NS 4096
#define ND 2048
#define NH 16
#define NDK 128
#define SCALE 0.08838834764831845f   // 1/sqrt(128)

typedef unsigned long long u64;

__device__ __forceinline__ void ffma2(u64& d, u64 a, u64 b) {
    asm("fma.rn.f32x2 %0, %1, %2, %0;" : "+l"(d) : "l"(a), "l"(b));
}
__device__ __forceinline__ u64 pack2(float x, float y) {
    u64 r; asm("mov.b64 %0, {%1, %2};" : "=l"(r) : "f"(x), "f"(y)); return r;
}
__device__ __forceinline__ float2 unpack2(u64 v) {
    float2 r; asm("mov.b64 {%0, %1}, %2;" : "=f"(r.x), "=f"(r.y) : "l"(v)); return r;
}

// -------- device scratch (no allocations allowed) --------
__device__ __align__(16) float g_qbp[16 * NB * ND];
__device__ __align__(16) float g_qb[NB * ND];                 // [b][h*128+d]
__device__ __align__(16) float g_A[NB * NH * ND];             // A[b][h][e]
__device__ __align__(16) float g_scores[NS * NB * NH];        // SCALE*(A.key), then += pos
__device__ float g_m[NB * NH];
__device__ float g_linv[NB * NH];
__device__ __align__(16) float g_upart[32 * NB * NH * ND];    // [jc(32)][b][h][e]
__device__ __align__(16) float g_xpart[16 * NB * ND];
__device__ __align__(16) float g_opart[16 * NB * ND];

// ---------------- K1: qb partials: (query @ Wq), g-split 16, MLP 8 ----------------
__global__ __launch_bounds__(256) void k_qbp(const float* __restrict__ query,
                                             const float* __restrict__ Wq) {
    int tid = threadIdx.x;
    int c   = blockIdx.x * 256 + tid;
    int g0  = blockIdx.y * 128;
    __shared__ float qs[8][128];
    for (int idx = tid; idx < 1024; idx += 256)
        qs[idx >> 7][idx & 127] = query[(idx >> 7) * ND + g0 + (idx & 127)];
    __syncthreads();
    float acc[8] = {0.f,0.f,0.f,0.f,0.f,0.f,0.f,0.f};
    for (int g = 0; g < 128; g += 8) {
        float w[8];
#pragma unroll
        for (int k2 = 0; k2 < 8; k2++) w[k2] = Wq[(g0 + g + k2) * ND + c];
#pragma unroll
        for (int k2 = 0; k2 < 8; k2++)
#pragma unroll
            for (int b = 0; b < 8; b++) acc[b] = fmaf(w[k2], qs[b][g + k2], acc[b]);
    }
#pragma unroll
    for (int b = 0; b < 8; b++) g_qbp[(blockIdx.y * 8 + b) * ND + c] = acc[b];
}

__global__ void k_qb(const float* __restrict__ q_bias) {
    int i = blockIdx.x * 256 + threadIdx.x;
    int c = i & (ND - 1);
    int b = i >> 11;
    float s = q_bias[c];
#pragma unroll
    for (int gc = 0; gc < 16; gc++) s += g_qbp[(gc * 8 + b) * ND + c];
    g_qb[i] = s;
}

// ---------------- K2: A[b][h][e] = sum_d Wk[e][h*128+d] * qb[b][h*128+d] ----------------
__global__ void k_A(const float* __restrict__ Wk) {
    int tid = threadIdx.x;           // 128
    int h   = blockIdx.y;
    int e0  = blockIdx.x * 128;
    __shared__ float qbs[8][128];
    __shared__ float wks[128][65];
    for (int idx = tid; idx < 1024; idx += 128)
        qbs[idx >> 7][idx & 127] = g_qb[(idx >> 7) * ND + h * NDK + (idx & 127)];
    float acc[8] = {0.f,0.f,0.f,0.f,0.f,0.f,0.f,0.f};
    for (int st = 0; st < 2; st++) {
        __syncthreads();
        for (int idx = tid; idx < 128 * 64; idx += 128) {
            int r = idx >> 6, cc = idx & 63;
            wks[r][cc] = Wk[(e0 + r) * ND + h * NDK + st * 64 + cc];
        }
        __syncthreads();
#pragma unroll 8
        for (int d = 0; d < 64; d++) {
            float w = wks[tid][d];
#pragma unroll
            for (int b = 0; b < 8; b++) acc[b] = fmaf(w, qbs[b][st * 64 + d], acc[b]);
        }
    }
    int e = e0 + tid;
#pragma unroll
    for (int b = 0; b < 8; b++) g_A[(b * NH + h) * ND + e] = acc[b];
}

// ---------------- K4: score pass — R7 fp32 SIMT, double-buffered kv prefetch ----------------
__global__ __launch_bounds__(512, 1) void k_scores(const float* __restrict__ key) {
    const int b = blockIdx.y;
    const int warp = threadIdx.x >> 5, lane = threadIdx.x & 31;
    const int jgrp  = warp >> 1;
    const int hbase = (warp & 1) * 8;
    const int j0w = blockIdx.x * 32 + jgrp * 4;
    __shared__ __align__(16) float As[16 * 2048];
    for (int idx = threadIdx.x; idx < 8192; idx += 512)
        ((float4*)As)[idx] = ((const float4*)(g_A + (size_t)b * NH * ND))[idx];
    __syncthreads();

    u64 acc[8][4];
#pragma unroll
    for (int hh = 0; hh < 8; hh++)
#pragma unroll
        for (int jj = 0; jj < 4; jj++) acc[hh][jj] = 0ull;

    const float* kbase = key + ((size_t)j0w * NB + b) * ND + lane * 4;
    const float* apb   = As + hbase * 2048 + lane * 4;

    ulonglong2 kva[4], kvb[4];
#pragma unroll
    for (int jj = 0; jj < 4; jj++)
        kva[jj] = *(const ulonglong2*)(kbase + (size_t)jj * (NB * ND));
#pragma unroll
    for (int jj = 0; jj < 4; jj++)
        kvb[jj] = *(const ulonglong2*)(kbase + (size_t)jj * (NB * ND) + 128);

#pragma unroll 1
    for (int e0 = 0; e0 < 2048; e0 += 256) {
        {
            const float* ap = apb + e0;
#pragma unroll
            for (int hh = 0; hh < 8; hh++) {
                ulonglong2 a = *(const ulonglong2*)(ap + hh * 2048);
#pragma unroll
                for (int jj = 0; jj < 4; jj++) {
                    ffma2(acc[hh][jj], a.x, kva[jj].x);
                    ffma2(acc[hh][jj], a.y, kva[jj].y);
                }
            }
        }
        {
            int en = (e0 + 256 < 2048) ? (e0 + 256) : 0;
#pragma unroll
            for (int jj = 0; jj < 4; jj++)
                kva[jj] = *(const ulonglong2*)(kbase + (size_t)jj * (NB * ND) + en);
        }
        {
            const float* ap = apb + e0 + 128;
#pragma unroll
            for (int hh = 0; hh < 8; hh++) {
                ulonglong2 a = *(const ulonglong2*)(ap + hh * 2048);
#pragma unroll
                for (int jj = 0; jj < 4; jj++) {
                    ffma2(acc[hh][jj], a.x, kvb[jj].x);
                    ffma2(acc[hh][jj], a.y, kvb[jj].y);
                }
            }
        }
        {
            int en = (e0 + 384 < 2048) ? (e0 + 384) : 0;
#pragma unroll
            for (int jj = 0; jj < 4; jj++)
                kvb[jj] = *(const ulonglong2*)(kbase + (size_t)jj * (NB * ND) + en);
        }
    }

    float v[32];
#pragma unroll
    for (int hh = 0; hh < 8; hh++)
#pragma unroll
        for (int jj = 0; jj < 4; jj++) {
            float2 p = unpack2(acc[hh][jj]);
            v[jj * 8 + hh] = p.x + p.y;
        }
    int n = 32;
#pragma unroll
    for (int half = 16; half >= 1; half >>= 1) {
        int m = n >> 1;
        bool upper = (lane & half) != 0;
#pragma unroll
        for (int i = 0; i < 16; i++) {
            if (i >= m) break;
            float send = upper ? v[i] : v[i + m];
            float recv = __shfl_xor_sync(0xffffffffu, send, half);
            v[i] = (upper ? v[i + m] : v[i]) + recv;
        }
        n = m;
    }
    int jj = lane >> 3, hh = lane & 7;
    g_scores[(j0w + jj) * 128 + b * 16 + hbase + hh] = v[0] * SCALE;
}

// ---------------- K3: g_scores += SCALE * (qb[b][h] . key_pos[j][h]) ----------------
__global__ __launch_bounds__(256) void k_pos(const float* __restrict__ key_pos) {
    const int warp = threadIdx.x >> 5, lane = threadIdx.x & 31;
    const int h  = blockIdx.y * 8 + warp;
    const int j0 = blockIdx.x * 4;

    u64 qb[8][2];
#pragma unroll
    for (int bb = 0; bb < 8; bb++) {
        ulonglong2 q = *(const ulonglong2*)&g_qb[bb * ND + h * NDK + lane * 4];
        qb[bb][0] = q.x; qb[bb][1] = q.y;
    }
    u64 acc[4][8];
#pragma unroll
    for (int jj = 0; jj < 4; jj++)
#pragma unroll
        for (int bb = 0; bb < 8; bb++) acc[jj][bb] = 0ull;

#pragma unroll
    for (int jj = 0; jj < 4; jj++) {
        ulonglong2 kp = *(const ulonglong2*)&key_pos[((size_t)(j0 + jj) * NH + h) * NDK + lane * 4];
#pragma unroll
        for (int bb = 0; bb < 8; bb++) {
            ffma2(acc[jj][bb], qb[bb][0], kp.x);
            ffma2(acc[jj][bb], qb[bb][1], kp.y);
        }
    }
    float v[32];
#pragma unroll
    for (int jj = 0; jj < 4; jj++)
#pragma unroll
        for (int bb = 0; bb < 8; bb++) {
            float2 p = unpack2(acc[jj][bb]);
            v[jj * 8 + bb] = p.x + p.y;
        }
    int n = 32;
#pragma unroll
    for (int half = 16; half >= 1; half >>= 1) {
        int m = n >> 1;
        bool upper = (lane & half) != 0;
#pragma unroll
        for (int i = 0; i < 16; i++) {
            if (i >= m) break;
            float send = upper ? v[i] : v[i + m];
            float recv = __shfl_xor_sync(0xffffffffu, send, half);
            v[i] = (upper ? v[i + m] : v[i]) + recv;
        }
        n = m;
    }
    int jj = lane >> 3, bb = lane & 7;
    int gi = (j0 + jj) * 128 + bb * 16 + h;
    g_scores[gi] = g_scores[gi] + v[0] * SCALE;   // accumulate pos in place
}

// ---------------- K5: softmax stats — block = (b, h-quad), float4 reads ----------------
__global__ __launch_bounds__(256) void k_softmax() {
    const int b = blockIdx.x >> 2, hq = blockIdx.x & 3;
    const int tid = threadIdx.x;
    const int base = b * 16 + hq * 4;
    __shared__ float red[4][256];

    float4 mx = make_float4(-1e30f, -1e30f, -1e30f, -1e30f);
    for (int j = tid; j < NS; j += 256) {
        float4 s = *(const float4*)&g_scores[j * 128 + base];
        mx.x = fmaxf(mx.x, s.x); mx.y = fmaxf(mx.y, s.y);
        mx.z = fmaxf(mx.z, s.z); mx.w = fmaxf(mx.w, s.w);
    }
    red[0][tid] = mx.x; red[1][tid] = mx.y; red[2][tid] = mx.z; red[3][tid] = mx.w;
    __syncthreads();
    for (int s = 128; s; s >>= 1) {
        if (tid < s)
#pragma unroll
            for (int q = 0; q < 4; q++)
                red[q][tid] = fmaxf(red[q][tid], red[q][tid + s]);
        __syncthreads();
    }
    float m0 = red[0][0], m1 = red[1][0], m2 = red[2][0], m3 = red[3][0];
    __syncthreads();

    float4 sum = make_float4(0.f, 0.f, 0.f, 0.f);
    for (int j = tid; j < NS; j += 256) {
        float4 s = *(const float4*)&g_scores[j * 128 + base];
        sum.x += __expf(s.x - m0); sum.y += __expf(s.y - m1);
        sum.z += __expf(s.z - m2); sum.w += __expf(s.w - m3);
    }
    red[0][tid] = sum.x; red[1][tid] = sum.y; red[2][tid] = sum.z; red[3][tid] = sum.w;
    __syncthreads();
    for (int s = 128; s; s >>= 1) {
        if (tid < s)
#pragma unroll
            for (int q = 0; q < 4; q++)
                red[q][tid] += red[q][tid + s];
        __syncthreads();
    }
    if (tid < 4) {
        float m = (tid == 0) ? m0 : (tid == 1) ? m1 : (tid == 2) ? m2 : m3;
        g_m[base + tid] = m;
        g_linv[base + tid] = 1.0f / red[tid][0];
    }
}

// ---------------- K6: value pass — float4, 4 e-cols/thread (R6 form) ----------------
__global__ __launch_bounds__(256) void k_value(const float* __restrict__ value) {
    const int tid = threadIdx.x;
    const int b = blockIdx.y, jc = blockIdx.z;
    const int e = blockIdx.x * 1024 + tid * 4;
    const int j0 = jc * 128;
    __shared__ __align__(16) u64 ws2[128 * 16];
    __shared__ float ms[16], ls[16];
    if (tid < 16) { ms[tid] = g_m[b * 16 + tid]; ls[tid] = g_linv[b * 16 + tid]; }
    __syncthreads();
    for (int idx = tid; idx < 2048; idx += 256) {
        int jl = idx >> 4, h = idx & 15;
        float w = __expf(g_scores[(j0 + jl) * 128 + b * 16 + h] - ms[h]) * ls[h];
        ws2[idx] = pack2(w, w);
    }
    __syncthreads();

    u64 acc[16][2];
#pragma unroll
    for (int h = 0; h < 16; h++) { acc[h][0] = 0ull; acc[h][1] = 0ull; }

    const float* vp = value + ((size_t)j0 * NB + b) * ND + e;
#pragma unroll 4
    for (int jl = 0; jl < 128; jl++) {
        ulonglong2 v2 = *(const ulonglong2*)(vp + (size_t)jl * (NB * ND));
        const ulonglong2* wr = (const ulonglong2*)(ws2 + jl * 16);
#pragma unroll
        for (int h2 = 0; h2 < 8; h2++) {
            ulonglong2 wp = wr[h2];
            ffma2(acc[2 * h2    ][0], wp.x, v2.x);
            ffma2(acc[2 * h2    ][1], wp.x, v2.y);
            ffma2(acc[2 * h2 + 1][0], wp.y, v2.x);
            ffma2(acc[2 * h2 + 1][1], wp.y, v2.y);
        }
    }
    int rb = (jc * 8 + b) * 16;
#pragma unroll
    for (int h = 0; h < 16; h++) {
        ulonglong2 o; o.x = acc[h][0]; o.y = acc[h][1];
        *(ulonglong2*)&g_upart[(size_t)(rb + h) * ND + e] = o;
    }
}

// ---------------- K7: x partials = u @ Wv (per head), e-split 16 ----------------
__global__ __launch_bounds__(128) void k_projv(const float* __restrict__ Wv) {
    int tid = threadIdx.x;   // 128 (= d)
    int h = blockIdx.y;
    int e0 = blockIdx.x * 128;
    __shared__ float us[8][128];
    for (int idx = tid; idx < 1024; idx += 128) {
        int bb = idx >> 7, el = idx & 127;
        float s = 0.f;
#pragma unroll
        for (int jc = 0; jc < 32; jc++)
            s += g_upart[(size_t)((jc * 8 + bb) * 16 + h) * ND + e0 + el];
        us[bb][el] = s;
    }
    __syncthreads();
    float acc[8] = {0.f,0.f,0.f,0.f,0.f,0.f,0.f,0.f};
    for (int el = 0; el < 128; el += 8) {
        float w[8];
#pragma unroll
        for (int k2 = 0; k2 < 8; k2++)
            w[k2] = Wv[(e0 + el + k2) * ND + h * NDK + tid];
#pragma unroll
        for (int k2 = 0; k2 < 8; k2++)
#pragma unroll
            for (int bb = 0; bb < 8; bb++) acc[bb] = fmaf(w[k2], us[bb][el + k2], acc[bb]);
    }
#pragma unroll
    for (int bb = 0; bb < 8; bb++)
        g_xpart[(blockIdx.x * 8 + bb) * ND + h * NDK + tid] = acc[bb];
}

// ---------------- K8: out partials = (xred + bv) @ Wo, xred fused into stage ----------------
__global__ __launch_bounds__(256) void k_out(const float* __restrict__ Wo,
                                             const float* __restrict__ bv) {
    int tid = threadIdx.x;
    int f = blockIdx.x * 256 + tid;
    int g0 = blockIdx.y * 128;
    __shared__ float xs[8][128];
    for (int idx = tid; idx < 1024; idx += 256) {
        int bb = idx >> 7, gl = idx & 127;
        float s = bv[g0 + gl];
#pragma unroll
        for (int ec = 0; ec < 16; ec++)
            s += g_xpart[(ec * 8 + bb) * ND + g0 + gl];
        xs[bb][gl] = s;
    }
    __syncthreads();
    float acc[8] = {0.f,0.f,0.f,0.f,0.f,0.f,0.f,0.f};
    for (int g = 0; g < 128; g += 8) {
        float w[8];
#pragma unroll
        for (int k2 = 0; k2 < 8; k2++) w[k2] = Wo[(g0 + g + k2) * ND + f];
#pragma unroll
        for (int k2 = 0; k2 < 8; k2++)
#pragma unroll
            for (int b = 0; b < 8; b++) acc[b] = fmaf(w[k2], xs[b][g + k2], acc[b]);
    }
#pragma unroll
    for (int b = 0; b < 8; b++) g_opart[(blockIdx.y * 8 + b) * ND + f] = acc[b];
}

__global__ void k_ored(const float* __restrict__ bo, float* __restrict__ out) {
    int i = blockIdx.x * 256 + threadIdx.x;
    int c = i & (ND - 1), b = i >> 11;
    float s = bo[c];
#pragma unroll
    for (int gc = 0; gc < 16; gc++) s += g_opart[(gc * 8 + b) * ND + c];
    out[i] = s;
}

extern "C" void kernel_launch(void* const* d_in, const int* in_sizes, int n_in,
                              void* d_out, int out_size) {
    const float* query   = (const float*)d_in[0];
    const float* key     = (const float*)d_in[1];
    const float* value   = (const float*)d_in[2];
    const float* Wq      = (const float*)d_in[3];
    const float* Wk      = (const float*)d_in[4];
    const float* Wv      = (const float*)d_in[5];
    const float* bv      = (const float*)d_in[6];
    const float* Wo      = (const float*)d_in[7];
    const float* bo      = (const float*)d_in[8];
    const float* key_pos = (const float*)d_in[9];
    const float* q_bias  = (const float*)d_in[10];
    float* out = (float*)d_out;

    // k_scores kept at launch idx 3 so the profiler's fixed slot lands on it.
    k_qbp    <<<dim3(8, 16),     256>>>(query, Wq);
    k_qb     <<<64,              256>>>(q_bias);
    k_A      <<<dim3(16, 16),    128>>>(Wk);
    k_scores <<<dim3(128, 8),    512>>>(key);
    k_pos    <<<dim3(1024, 2),   256>>>(key_pos);
    k_softmax<<<32,              256>>>();
    k_value  <<<dim3(2, 8, 32),  256>>>(value);
    k_projv  <<<dim3(16, 16),    128>>>(Wv);
    k_out    <<<dim3(8, 16),     256>>>(Wo, bv);
    k_ored   <<<64,              256>>>(bo, out);
}

// round 16
// speedup vs baseline: 1.3472x; 1.0320x over previous
#include <cuda_runtime.h>
#include <math.h>
#include <stdint.h>

// Shapes
#define NB 8
#define NS 4096
#define ND 2048
#define NH 16
#define NDK 128
#define SCALE 0.08838834764831845f   // 1/sqrt(128)

typedef unsigned long long u64;

__device__ __forceinline__ void ffma2(u64& d, u64 a, u64 b) {
    asm("fma.rn.f32x2 %0, %1, %2, %0;" : "+l"(d) : "l"(a), "l"(b));
}
__device__ __forceinline__ u64 pack2(float x, float y) {
    u64 r; asm("mov.b64 %0, {%1, %2};" : "=l"(r) : "f"(x), "f"(y)); return r;
}
__device__ __forceinline__ float2 unpack2(u64 v) {
    float2 r; asm("mov.b64 {%0, %1}, %2;" : "=f"(r.x), "=f"(r.y) : "l"(v)); return r;
}
// pack (x0,x1) -> bf16x2, x0 in LOW half
__device__ __forceinline__ uint32_t bf16x2_of(float x0, float x1) {
    uint32_t r; asm("cvt.rn.bf16x2.f32 %0, %2, %1;" : "=r"(r) : "f"(x0), "f"(x1)); return r;
}
__device__ __forceinline__ void cvt_split(float2 f, uint32_t& hi, uint32_t& lo) {
    hi = bf16x2_of(f.x, f.y);
    float rx = f.x - __uint_as_float(hi << 16);
    float ry = f.y - __uint_as_float(hi & 0xffff0000u);
    lo = bf16x2_of(rx, ry);
}
__device__ __forceinline__ void mma_bf16(float& d0, float& d1, float& d2, float& d3,
                                         uint32_t a0, uint32_t a1, uint32_t a2, uint32_t a3,
                                         uint32_t b0, uint32_t b1) {
    asm("mma.sync.aligned.m16n8k16.row.col.f32.bf16.bf16.f32 "
        "{%0,%1,%2,%3}, {%4,%5,%6,%7}, {%8,%9}, {%0,%1,%2,%3};"
        : "+f"(d0), "+f"(d1), "+f"(d2), "+f"(d3)
        : "r"(a0), "r"(a1), "r"(a2), "r"(a3), "r"(b0), "r"(b1));
}

// -------- device scratch (no allocations allowed) --------
__device__ __align__(16) float g_qbp[16 * NB * ND];
__device__ __align__(16) float g_qb[NB * ND];                 // [b][h*128+d]
__device__ __align__(16) float g_A[NB * NH * ND];             // A[b][h][e]
// packed bf16 B-fragments of g_A: [b][h][chunk16(128)][slot(8)]
// slot 2t = k-pair t, slot 2t+1 = k-pair t+4 (chunk16 = 16 consecutive e)
__device__ __align__(16) uint32_t g_Bh[NB * NH * 128 * 8];
__device__ __align__(16) uint32_t g_Bl[NB * NH * 128 * 8];
__device__ __align__(16) float g_scores[NS * NB * NH];
__device__ float g_m[NB * NH];
__device__ float g_linv[NB * NH];
__device__ __align__(16) float g_upart[32 * NB * NH * ND];    // [jc(32)][b][h][e]
__device__ __align__(16) float g_xpart[16 * NB * ND];
__device__ __align__(16) float g_opart[16 * NB * ND];

// ---------------- K1: qb partials: (query @ Wq), g-split 16, MLP 8 ----------------
__global__ __launch_bounds__(256) void k_qbp(const float* __restrict__ query,
                                             const float* __restrict__ Wq) {
    int tid = threadIdx.x;
    int c   = blockIdx.x * 256 + tid;
    int g0  = blockIdx.y * 128;
    __shared__ float qs[8][128];
    for (int idx = tid; idx < 1024; idx += 256)
        qs[idx >> 7][idx & 127] = query[(idx >> 7) * ND + g0 + (idx & 127)];
    __syncthreads();
    float acc[8] = {0.f,0.f,0.f,0.f,0.f,0.f,0.f,0.f};
    for (int g = 0; g < 128; g += 8) {
        float w[8];
#pragma unroll
        for (int k2 = 0; k2 < 8; k2++) w[k2] = Wq[(g0 + g + k2) * ND + c];
#pragma unroll
        for (int k2 = 0; k2 < 8; k2++)
#pragma unroll
            for (int b = 0; b < 8; b++) acc[b] = fmaf(w[k2], qs[b][g + k2], acc[b]);
    }
#pragma unroll
    for (int b = 0; b < 8; b++) g_qbp[(blockIdx.y * 8 + b) * ND + c] = acc[b];
}

__global__ void k_qb(const float* __restrict__ q_bias) {
    int i = blockIdx.x * 256 + threadIdx.x;
    int c = i & (ND - 1);
    int b = i >> 11;
    float s = q_bias[c];
#pragma unroll
    for (int gc = 0; gc < 16; gc++) s += g_qbp[(gc * 8 + b) * ND + c];
    g_qb[i] = s;
}

// ---------------- K2: A[b][h][e] = Wk.qb, plus bf16 hi/lo B-fragment packing ----------------
__global__ void k_A(const float* __restrict__ Wk) {
    int tid = threadIdx.x;           // 128
    int h   = blockIdx.y;
    int e0  = blockIdx.x * 128;
    __shared__ float qbs[8][128];
    __shared__ float wks[128][65];
    __shared__ float as2[8][128];
    for (int idx = tid; idx < 1024; idx += 128)
        qbs[idx >> 7][idx & 127] = g_qb[(idx >> 7) * ND + h * NDK + (idx & 127)];
    float acc[8] = {0.f,0.f,0.f,0.f,0.f,0.f,0.f,0.f};
    for (int st = 0; st < 2; st++) {
        __syncthreads();
        for (int idx = tid; idx < 128 * 64; idx += 128) {
            int r = idx >> 6, cc = idx & 63;
            wks[r][cc] = Wk[(e0 + r) * ND + h * NDK + st * 64 + cc];
        }
        __syncthreads();
#pragma unroll 8
        for (int d = 0; d < 64; d++) {
            float w = wks[tid][d];
#pragma unroll
            for (int b = 0; b < 8; b++) acc[b] = fmaf(w, qbs[b][st * 64 + d], acc[b]);
        }
    }
    int e = e0 + tid;
#pragma unroll
    for (int b = 0; b < 8; b++) {
        g_A[(b * NH + h) * ND + e] = acc[b];
        as2[b][tid] = acc[b];
    }
    __syncthreads();
#pragma unroll
    for (int it = 0; it < 4; it++) {
        int idx = tid + it * 128;            // 0..511 = b(8) x chunk16(8) x slot(8)
        int bb = idx >> 6, c = (idx >> 3) & 7, s = idx & 7;
        int p = (s >> 1) + ((s & 1) << 2);   // slot->k-pair
        int ep = c * 16 + 2 * p;
        float2 f = make_float2(as2[bb][ep], as2[bb][ep + 1]);
        uint32_t hi, lo;
        cvt_split(f, hi, lo);
        int off = ((bb * NH + h) * 128 + blockIdx.x * 8 + c) * 8 + s;
        g_Bh[off] = hi;
        g_Bl[off] = lo;
    }
}

// ---------------- K4: score pass — mma.sync v4: 64j CTA, 64e chunks, bf16 smem ----------------
// CTA = 256 thr / 8 warps; warp = (m-tile mt = warp>>1: 16 j) x (n-half nh = warp&1: 8 h).
// Chunk = 64 e: coalesced LDG (256B/row), cvt -> Sh/Sl (pad 36: conflict-free frag LDS),
// double-buffered, LDG for c+1 issued before computing c. B from prepacked g_Bh/g_Bl.
__global__ __launch_bounds__(256) void k_scores(const float* __restrict__ key) {
    const int b = blockIdx.y;
    const int tid = threadIdx.x;
    const int warp = tid >> 5, lane = tid & 31;
    const int g = lane >> 2, t = lane & 3;
    const int mt = warp >> 1, nh = warp & 1;
    const int j0 = blockIdx.x * 64;

    __shared__ __align__(16) uint32_t Sh[2][64][36];   // 18 KB
    __shared__ __align__(16) uint32_t Sl[2][64][36];   // 18 KB

    // staging geometry: seg = tid + it*256, row = seg>>4 (64 rows), c16 = seg&15 (16B units)
    const int srow = tid >> 2;           // base rows for it: rows srow + it*64? No:
    // seg>>4 with tid in [0,256): it=0 rows 0..15, it=1 rows 16..31, ... -> row = (tid>>4) + it*16
    const int rrow = tid >> 4;           // 0..15
    const int rcol = tid & 15;           // 0..15 (16B units within 256B row-chunk)

    float4 pf[4];
    auto LDG_CHUNK = [&](int ch) {
#pragma unroll
        for (int it = 0; it < 4; it++) {
            int row = rrow + it * 16;
            pf[it] = *(const float4*)(key + ((size_t)(j0 + row) * NB + b) * ND
                                          + ch * 64 + rcol * 4);
        }
    };
    auto STS_CHUNK = [&](int buf) {
#pragma unroll
        for (int it = 0; it < 4; it++) {
            int row = rrow + it * 16;
            uint32_t h0, l0, h1, l1;
            cvt_split(make_float2(pf[it].x, pf[it].y), h0, l0);
            cvt_split(make_float2(pf[it].z, pf[it].w), h1, l1);
            Sh[buf][row][rcol * 2]     = h0;
            Sh[buf][row][rcol * 2 + 1] = h1;
            Sl[buf][row][rcol * 2]     = l0;
            Sl[buf][row][rcol * 2 + 1] = l1;
        }
    };

    float d[4] = {0.f, 0.f, 0.f, 0.f};

    // B-fragment pointers (R13-validated layout); n rows = nh*8 + g
    const uint32_t* bhp = g_Bh + ((size_t)(b * NH + nh * 8 + g) * 128) * 8 + 2 * t;
    const uint32_t* blp = g_Bl + ((size_t)(b * NH + nh * 8 + g) * 128) * 8 + 2 * t;

    LDG_CHUNK(0); STS_CHUNK(0);
    __syncthreads();

#pragma unroll 1
    for (int ch = 0; ch < 32; ch++) {
        const int buf = ch & 1;
        if (ch + 1 < 32) LDG_CHUNK(ch + 1);   // hide LDG under compute

        const int r0 = mt * 16 + g;
#pragma unroll
        for (int ks = 0; ks < 4; ks++) {
            uint32_t ah0 = Sh[buf][r0][ks * 8 + t];
            uint32_t ah1 = Sh[buf][r0 + 8][ks * 8 + t];
            uint32_t ah2 = Sh[buf][r0][ks * 8 + t + 4];
            uint32_t ah3 = Sh[buf][r0 + 8][ks * 8 + t + 4];
            uint32_t al0 = Sl[buf][r0][ks * 8 + t];
            uint32_t al1 = Sl[buf][r0 + 8][ks * 8 + t];
            uint32_t al2 = Sl[buf][r0][ks * 8 + t + 4];
            uint32_t al3 = Sl[buf][r0 + 8][ks * 8 + t + 4];
            int c2 = ch * 4 + ks;
            uint2 Bh2 = *(const uint2*)(bhp + c2 * 8);
            uint2 Bl2 = *(const uint2*)(blp + c2 * 8);
            mma_bf16(d[0], d[1], d[2], d[3], ah0, ah1, ah2, ah3, Bh2.x, Bh2.y);
            mma_bf16(d[0], d[1], d[2], d[3], ah0, ah1, ah2, ah3, Bl2.x, Bl2.y);
            mma_bf16(d[0], d[1], d[2], d[3], al0, al1, al2, al3, Bh2.x, Bh2.y);
        }

        if (ch + 1 < 32) STS_CHUNK(buf ^ 1);
        __syncthreads();
    }

    // D: c0=(g,2t) c1=(g,2t+1) c2=(g+8,2t) c3=(g+8,2t+1) within 16x8 tile
    const int jA = j0 + mt * 16 + g, jB = jA + 8;
    const int hb = b * 16 + nh * 8;
    g_scores[jA * 128 + hb + 2 * t]     = d[0] * SCALE;
    g_scores[jA * 128 + hb + 2 * t + 1] = d[1] * SCALE;
    g_scores[jB * 128 + hb + 2 * t]     = d[2] * SCALE;
    g_scores[jB * 128 + hb + 2 * t + 1] = d[3] * SCALE;
}

// ---------------- K3: g_scores += SCALE * (qb[b][h] . key_pos[j][h]) ----------------
__global__ __launch_bounds__(256) void k_pos(const float* __restrict__ key_pos) {
    const int warp = threadIdx.x >> 5, lane = threadIdx.x & 31;
    const int h  = blockIdx.y * 8 + warp;
    const int j0 = blockIdx.x * 4;

    u64 qb[8][2];
#pragma unroll
    for (int bb = 0; bb < 8; bb++) {
        ulonglong2 q = *(const ulonglong2*)&g_qb[bb * ND + h * NDK + lane * 4];
        qb[bb][0] = q.x; qb[bb][1] = q.y;
    }
    u64 acc[4][8];
#pragma unroll
    for (int jj = 0; jj < 4; jj++)
#pragma unroll
        for (int bb = 0; bb < 8; bb++) acc[jj][bb] = 0ull;

#pragma unroll
    for (int jj = 0; jj < 4; jj++) {
        ulonglong2 kp = *(const ulonglong2*)&key_pos[((size_t)(j0 + jj) * NH + h) * NDK + lane * 4];
#pragma unroll
        for (int bb = 0; bb < 8; bb++) {
            ffma2(acc[jj][bb], qb[bb][0], kp.x);
            ffma2(acc[jj][bb], qb[bb][1], kp.y);
        }
    }
    float v[32];
#pragma unroll
    for (int jj = 0; jj < 4; jj++)
#pragma unroll
        for (int bb = 0; bb < 8; bb++) {
            float2 p = unpack2(acc[jj][bb]);
            v[jj * 8 + bb] = p.x + p.y;
        }
    int n = 32;
#pragma unroll
    for (int half = 16; half >= 1; half >>= 1) {
        int m = n >> 1;
        bool upper = (lane & half) != 0;
#pragma unroll
        for (int i = 0; i < 16; i++) {
            if (i >= m) break;
            float send = upper ? v[i] : v[i + m];
            float recv = __shfl_xor_sync(0xffffffffu, send, half);
            v[i] = (upper ? v[i + m] : v[i]) + recv;
        }
        n = m;
    }
    int jj = lane >> 3, bb = lane & 7;
    int gi = (j0 + jj) * 128 + bb * 16 + h;
    g_scores[gi] = g_scores[gi] + v[0] * SCALE;
}

// ---------------- K5: softmax stats — block = (b, h-quad), float4 reads ----------------
__global__ __launch_bounds__(256) void k_softmax() {
    const int b = blockIdx.x >> 2, hq = blockIdx.x & 3;
    const int tid = threadIdx.x;
    const int base = b * 16 + hq * 4;
    __shared__ float red[4][256];

    float4 mx = make_float4(-1e30f, -1e30f, -1e30f, -1e30f);
    for (int j = tid; j < NS; j += 256) {
        float4 s = *(const float4*)&g_scores[j * 128 + base];
        mx.x = fmaxf(mx.x, s.x); mx.y = fmaxf(mx.y, s.y);
        mx.z = fmaxf(mx.z, s.z); mx.w = fmaxf(mx.w, s.w);
    }
    red[0][tid] = mx.x; red[1][tid] = mx.y; red[2][tid] = mx.z; red[3][tid] = mx.w;
    __syncthreads();
    for (int s = 128; s; s >>= 1) {
        if (tid < s)
#pragma unroll
            for (int q = 0; q < 4; q++)
                red[q][tid] = fmaxf(red[q][tid], red[q][tid + s]);
        __syncthreads();
    }
    float m0 = red[0][0], m1 = red[1][0], m2 = red[2][0], m3 = red[3][0];
    __syncthreads();

    float4 sum = make_float4(0.f, 0.f, 0.f, 0.f);
    for (int j = tid; j < NS; j += 256) {
        float4 s = *(const float4*)&g_scores[j * 128 + base];
        sum.x += __expf(s.x - m0); sum.y += __expf(s.y - m1);
        sum.z += __expf(s.z - m2); sum.w += __expf(s.w - m3);
    }
    red[0][tid] = sum.x; red[1][tid] = sum.y; red[2][tid] = sum.z; red[3][tid] = sum.w;
    __syncthreads();
    for (int s = 128; s; s >>= 1) {
        if (tid < s)
#pragma unroll
            for (int q = 0; q < 4; q++)
                red[q][tid] += red[q][tid + s];
        __syncthreads();
    }
    if (tid < 4) {
        float m = (tid == 0) ? m0 : (tid == 1) ? m1 : (tid == 2) ? m2 : m3;
        g_m[base + tid] = m;
        g_linv[base + tid] = 1.0f / red[tid][0];
    }
}

// ---------------- K6: value pass — float4, 4 e-cols/thread ----------------
__global__ __launch_bounds__(256) void k_value(const float* __restrict__ value) {
    const int tid = threadIdx.x;
    const int b = blockIdx.y, jc = blockIdx.z;
    const int e = blockIdx.x * 1024 + tid * 4;
    const int j0 = jc * 128;
    __shared__ __align__(16) u64 ws2[128 * 16];
    __shared__ float ms[16], ls[16];
    if (tid < 16) { ms[tid] = g_m[b * 16 + tid]; ls[tid] = g_linv[b * 16 + tid]; }
    __syncthreads();
    for (int idx = tid; idx < 2048; idx += 256) {
        int jl = idx >> 4, h = idx & 15;
        float w = __expf(g_scores[(j0 + jl) * 128 + b * 16 + h] - ms[h]) * ls[h];
        ws2[idx] = pack2(w, w);
    }
    __syncthreads();

    u64 acc[16][2];
#pragma unroll
    for (int h = 0; h < 16; h++) { acc[h][0] = 0ull; acc[h][1] = 0ull; }

    const float* vp = value + ((size_t)j0 * NB + b) * ND + e;
#pragma unroll 4
    for (int jl = 0; jl < 128; jl++) {
        ulonglong2 v2 = *(const ulonglong2*)(vp + (size_t)jl * (NB * ND));
        const ulonglong2* wr = (const ulonglong2*)(ws2 + jl * 16);
#pragma unroll
        for (int h2 = 0; h2 < 8; h2++) {
            ulonglong2 wp = wr[h2];
            ffma2(acc[2 * h2    ][0], wp.x, v2.x);
            ffma2(acc[2 * h2    ][1], wp.x, v2.y);
            ffma2(acc[2 * h2 + 1][0], wp.y, v2.x);
            ffma2(acc[2 * h2 + 1][1], wp.y, v2.y);
        }
    }
    int rb = (jc * 8 + b) * 16;
#pragma unroll
    for (int h = 0; h < 16; h++) {
        ulonglong2 o; o.x = acc[h][0]; o.y = acc[h][1];
        *(ulonglong2*)&g_upart[(size_t)(rb + h) * ND + e] = o;
    }
}

// ---------------- K7: x partials = u @ Wv (per head), e-split 16 ----------------
__global__ __launch_bounds__(128) void k_projv(const float* __restrict__ Wv) {
    int tid = threadIdx.x;   // 128 (= d)
    int h = blockIdx.y;
    int e0 = blockIdx.x * 128;
    __shared__ float us[8][128];
    for (int idx = tid; idx < 1024; idx += 128) {
        int bb = idx >> 7, el = idx & 127;
        float s = 0.f;
#pragma unroll
        for (int jc = 0; jc < 32; jc++)
            s += g_upart[(size_t)((jc * 8 + bb) * 16 + h) * ND + e0 + el];
        us[bb][el] = s;
    }
    __syncthreads();
    float acc[8] = {0.f,0.f,0.f,0.f,0.f,0.f,0.f,0.f};
    for (int el = 0; el < 128; el += 8) {
        float w[8];
#pragma unroll
        for (int k2 = 0; k2 < 8; k2++)
            w[k2] = Wv[(e0 + el + k2) * ND + h * NDK + tid];
#pragma unroll
        for (int k2 = 0; k2 < 8; k2++)
#pragma unroll
            for (int bb = 0; bb < 8; bb++) acc[bb] = fmaf(w[k2], us[bb][el + k2], acc[bb]);
    }
#pragma unroll
    for (int bb = 0; bb < 8; bb++)
        g_xpart[(blockIdx.x * 8 + bb) * ND + h * NDK + tid] = acc[bb];
}

// ---------------- K8: out partials = (xred + bv) @ Wo, xred fused into stage ----------------
__global__ __launch_bounds__(256) void k_out(const float* __restrict__ Wo,
                                             const float* __restrict__ bv) {
    int tid = threadIdx.x;
    int f = blockIdx.x * 256 + tid;
    int g0 = blockIdx.y * 128;
    __shared__ float xs[8][128];
    for (int idx = tid; idx < 1024; idx += 256) {
        int bb = idx >> 7, gl = idx & 127;
        float s = bv[g0 + gl];
#pragma unroll
        for (int ec = 0; ec < 16; ec++)
            s += g_xpart[(ec * 8 + bb) * ND + g0 + gl];
        xs[bb][gl] = s;
    }
    __syncthreads();
    float acc[8] = {0.f,0.f,0.f,0.f,0.f,0.f,0.f,0.f};
    for (int g = 0; g < 128; g += 8) {
        float w[8];
#pragma unroll
        for (int k2 = 0; k2 < 8; k2++) w[k2] = Wo[(g0 + g + k2) * ND + f];
#pragma unroll
        for (int k2 = 0; k2 < 8; k2++)
#pragma unroll
            for (int b = 0; b < 8; b++) acc[b] = fmaf(w[k2], xs[b][g + k2], acc[b]);
    }
#pragma unroll
    for (int b = 0; b < 8; b++) g_opart[(blockIdx.y * 8 + b) * ND + f] = acc[b];
}

__global__ void k_ored(const float* __restrict__ bo, float* __restrict__ out) {
    int i = blockIdx.x * 256 + threadIdx.x;
    int c = i & (ND - 1), b = i >> 11;
    float s = bo[c];
#pragma unroll
    for (int gc = 0; gc < 16; gc++) s += g_opart[(gc * 8 + b) * ND + c];
    out[i] = s;
}

extern "C" void kernel_launch(void* const* d_in, const int* in_sizes, int n_in,
                              void* d_out, int out_size) {
    const float* query   = (const float*)d_in[0];
    const float* key     = (const float*)d_in[1];
    const float* value   = (const float*)d_in[2];
    const float* Wq      = (const float*)d_in[3];
    const float* Wk      = (const float*)d_in[4];
    const float* Wv      = (const float*)d_in[5];
    const float* bv      = (const float*)d_in[6];
    const float* Wo      = (const float*)d_in[7];
    const float* bo      = (const float*)d_in[8];
    const float* key_pos = (const float*)d_in[9];
    const float* q_bias  = (const float*)d_in[10];
    float* out = (float*)d_out;

    // k_scores kept at launch idx 3 so the profiler's fixed slot lands on it.
    k_qbp    <<<dim3(8, 16),     256>>>(query, Wq);
    k_qb     <<<64,              256>>>(q_bias);
    k_A      <<<dim3(16, 16),    128>>>(Wk);
    k_scores <<<dim3(64, 8),     256>>>(key);
    k_pos    <<<dim3(1024, 2),   256>>>(key_pos);
    k_softmax<<<32,              256>>>();
    k_value  <<<dim3(2, 8, 32),  256>>>(value);
    k_projv  <<<dim3(16, 16),    128>>>(Wv);
    k_out    <<<dim3(8, 16),     256>>>(Wo, bv);
    k_ored   <<<64,              256>>>(bo, out);
}

// round 17
// speedup vs baseline: 1.3833x; 1.0267x over previous
#include <cuda_runtime.h>
#include <math.h>
#include <stdint.h>

// Shapes
#define NB 8
#define NS 4096
#define ND 2048
#define NH 16
#define NDK 128
#define SCALE 0.08838834764831845f   // 1/sqrt(128)

typedef unsigned long long u64;

__device__ __forceinline__ void ffma2(u64& d, u64 a, u64 b) {
    asm("fma.rn.f32x2 %0, %1, %2, %0;" : "+l"(d) : "l"(a), "l"(b));
}
__device__ __forceinline__ u64 pack2(float x, float y) {
    u64 r; asm("mov.b64 %0, {%1, %2};" : "=l"(r) : "f"(x), "f"(y)); return r;
}
__device__ __forceinline__ float2 unpack2(u64 v) {
    float2 r; asm("mov.b64 {%0, %1}, %2;" : "=f"(r.x), "=f"(r.y) : "l"(v)); return r;
}
// pack (x0,x1) -> bf16x2, x0 in LOW half
__device__ __forceinline__ uint32_t bf16x2_of(float x0, float x1) {
    uint32_t r; asm("cvt.rn.bf16x2.f32 %0, %2, %1;" : "=r"(r) : "f"(x0), "f"(x1)); return r;
}
__device__ __forceinline__ void cvt_split(float2 f, uint32_t& hi, uint32_t& lo) {
    hi = bf16x2_of(f.x, f.y);
    float rx = f.x - __uint_as_float(hi << 16);
    float ry = f.y - __uint_as_float(hi & 0xffff0000u);
    lo = bf16x2_of(rx, ry);
}
__device__ __forceinline__ void mma_bf16(float& d0, float& d1, float& d2, float& d3,
                                         uint32_t a0, uint32_t a1, uint32_t a2, uint32_t a3,
                                         uint32_t b0, uint32_t b1) {
    asm("mma.sync.aligned.m16n8k16.row.col.f32.bf16.bf16.f32 "
        "{%0,%1,%2,%3}, {%4,%5,%6,%7}, {%8,%9}, {%0,%1,%2,%3};"
        : "+f"(d0), "+f"(d1), "+f"(d2), "+f"(d3)
        : "r"(a0), "r"(a1), "r"(a2), "r"(a3), "r"(b0), "r"(b1));
}

// -------- device scratch (no allocations allowed) --------
__device__ __align__(16) float g_qbp[16 * NB * ND];
__device__ __align__(16) float g_qb[NB * ND];                 // [b][h*128+d]
__device__ __align__(16) float g_A[NB * NH * ND];             // A[b][h][e]
// packed bf16 B-fragments of g_A: [b][h][chunk16(128)][slot(8)]
__device__ __align__(16) uint32_t g_Bh[NB * NH * 128 * 8];
__device__ __align__(16) uint32_t g_Bl[NB * NH * 128 * 8];
__device__ __align__(16) float g_scores[NS * NB * NH];
__device__ float g_m[NB * NH];
__device__ float g_linv[NB * NH];
__device__ __align__(16) float g_upart[32 * NB * NH * ND];    // [jc(32)][b][h][e]
__device__ __align__(16) float g_xpart[16 * NB * ND];
__device__ __align__(16) float g_opart[16 * NB * ND];

// ---------------- K1: qb partials: (query @ Wq), g-split 16, MLP 8 ----------------
__global__ __launch_bounds__(256) void k_qbp(const float* __restrict__ query,
                                             const float* __restrict__ Wq) {
    int tid = threadIdx.x;
    int c   = blockIdx.x * 256 + tid;
    int g0  = blockIdx.y * 128;
    __shared__ float qs[8][128];
    for (int idx = tid; idx < 1024; idx += 256)
        qs[idx >> 7][idx & 127] = query[(idx >> 7) * ND + g0 + (idx & 127)];
    __syncthreads();
    float acc[8] = {0.f,0.f,0.f,0.f,0.f,0.f,0.f,0.f};
    for (int g = 0; g < 128; g += 8) {
        float w[8];
#pragma unroll
        for (int k2 = 0; k2 < 8; k2++) w[k2] = Wq[(g0 + g + k2) * ND + c];
#pragma unroll
        for (int k2 = 0; k2 < 8; k2++)
#pragma unroll
            for (int b = 0; b < 8; b++) acc[b] = fmaf(w[k2], qs[b][g + k2], acc[b]);
    }
#pragma unroll
    for (int b = 0; b < 8; b++) g_qbp[(blockIdx.y * 8 + b) * ND + c] = acc[b];
}

__global__ void k_qb(const float* __restrict__ q_bias) {
    int i = blockIdx.x * 256 + threadIdx.x;
    int c = i & (ND - 1);
    int b = i >> 11;
    float s = q_bias[c];
#pragma unroll
    for (int gc = 0; gc < 16; gc++) s += g_qbp[(gc * 8 + b) * ND + c];
    g_qb[i] = s;
}

// ---------------- K2: A[b][h][e] = Wk.qb, plus bf16 hi/lo B-fragment packing ----------------
__global__ void k_A(const float* __restrict__ Wk) {
    int tid = threadIdx.x;           // 128
    int h   = blockIdx.y;
    int e0  = blockIdx.x * 128;
    __shared__ float qbs[8][128];
    __shared__ float wks[128][65];
    __shared__ float as2[8][128];
    for (int idx = tid; idx < 1024; idx += 128)
        qbs[idx >> 7][idx & 127] = g_qb[(idx >> 7) * ND + h * NDK + (idx & 127)];
    float acc[8] = {0.f,0.f,0.f,0.f,0.f,0.f,0.f,0.f};
    for (int st = 0; st < 2; st++) {
        __syncthreads();
        for (int idx = tid; idx < 128 * 64; idx += 128) {
            int r = idx >> 6, cc = idx & 63;
            wks[r][cc] = Wk[(e0 + r) * ND + h * NDK + st * 64 + cc];
        }
        __syncthreads();
#pragma unroll 8
        for (int d = 0; d < 64; d++) {
            float w = wks[tid][d];
#pragma unroll
            for (int b = 0; b < 8; b++) acc[b] = fmaf(w, qbs[b][st * 64 + d], acc[b]);
        }
    }
    int e = e0 + tid;
#pragma unroll
    for (int b = 0; b < 8; b++) {
        g_A[(b * NH + h) * ND + e] = acc[b];
        as2[b][tid] = acc[b];
    }
    __syncthreads();
#pragma unroll
    for (int it = 0; it < 4; it++) {
        int idx = tid + it * 128;            // 0..511 = b(8) x chunk16(8) x slot(8)
        int bb = idx >> 6, c = (idx >> 3) & 7, s = idx & 7;
        int p = (s >> 1) + ((s & 1) << 2);   // slot->k-pair
        int ep = c * 16 + 2 * p;
        float2 f = make_float2(as2[bb][ep], as2[bb][ep + 1]);
        uint32_t hi, lo;
        cvt_split(f, hi, lo);
        int off = ((bb * NH + h) * 128 + blockIdx.x * 8 + c) * 8 + s;
        g_Bh[off] = hi;
        g_Bl[off] = lo;
    }
}

// ---------------- K4: score pass — mma v5: warp = 16j x 16h, 32e chunks ----------------
// CTA = 128 thr / 4 warps / 64 j. A-fragments loaded ONCE per warp, serve both n-tiles.
// Smem stride 20 words (16 data + 4 pad): frag LDS bank set g*20+t mod 32 all-distinct.
__global__ __launch_bounds__(128) void k_scores(const float* __restrict__ key) {
    const int b = blockIdx.y;
    const int tid = threadIdx.x;
    const int warp = tid >> 5, lane = tid & 31;
    const int g = lane >> 2, t = lane & 3;
    const int j0 = blockIdx.x * 64;

    __shared__ __align__(16) uint32_t Sh[2][64][20];   // 10.25 KB
    __shared__ __align__(16) uint32_t Sl[2][64][20];   // 10.25 KB

    // staging: 64 rows x 32 e (128 B/row) = 512 float4 segs / 128 thr = 4 per thread
    const int rrow = tid >> 3;           // 0..15
    const int rcol = tid & 7;            // 0..7 (float4 units)

    float4 pf[4];
    auto LDG_CHUNK = [&](int ch) {
#pragma unroll
        for (int it = 0; it < 4; it++) {
            int row = rrow + it * 16;
            pf[it] = *(const float4*)(key + ((size_t)(j0 + row) * NB + b) * ND
                                          + ch * 32 + rcol * 4);
        }
    };
    auto STS_CHUNK = [&](int buf) {
#pragma unroll
        for (int it = 0; it < 4; it++) {
            int row = rrow + it * 16;
            uint32_t h0, l0, h1, l1;
            cvt_split(make_float2(pf[it].x, pf[it].y), h0, l0);
            cvt_split(make_float2(pf[it].z, pf[it].w), h1, l1);
            Sh[buf][row][rcol * 2]     = h0;
            Sh[buf][row][rcol * 2 + 1] = h1;
            Sl[buf][row][rcol * 2]     = l0;
            Sl[buf][row][rcol * 2 + 1] = l1;
        }
    };

    float d0[4] = {0.f, 0.f, 0.f, 0.f};
    float d1[4] = {0.f, 0.f, 0.f, 0.f};

    const uint32_t* bh0 = g_Bh + ((size_t)(b * NH + g)     * 128) * 8 + 2 * t;
    const uint32_t* bh1 = g_Bh + ((size_t)(b * NH + 8 + g) * 128) * 8 + 2 * t;
    const uint32_t* bl0 = g_Bl + ((size_t)(b * NH + g)     * 128) * 8 + 2 * t;
    const uint32_t* bl1 = g_Bl + ((size_t)(b * NH + 8 + g) * 128) * 8 + 2 * t;

    const int r0 = warp * 16 + g;

    LDG_CHUNK(0); STS_CHUNK(0);
    __syncthreads();

#pragma unroll 1
    for (int ch = 0; ch < 64; ch++) {
        const int buf = ch & 1;
        if (ch + 1 < 64) LDG_CHUNK(ch + 1);   // hide LDG under compute

#pragma unroll
        for (int ks = 0; ks < 2; ks++) {
            uint32_t ah0 = Sh[buf][r0][ks * 8 + t];
            uint32_t ah1 = Sh[buf][r0 + 8][ks * 8 + t];
            uint32_t ah2 = Sh[buf][r0][ks * 8 + t + 4];
            uint32_t ah3 = Sh[buf][r0 + 8][ks * 8 + t + 4];
            uint32_t al0 = Sl[buf][r0][ks * 8 + t];
            uint32_t al1 = Sl[buf][r0 + 8][ks * 8 + t];
            uint32_t al2 = Sl[buf][r0][ks * 8 + t + 4];
            uint32_t al3 = Sl[buf][r0 + 8][ks * 8 + t + 4];
            int c2 = ch * 2 + ks;
            uint2 B0h = *(const uint2*)(bh0 + c2 * 8);
            uint2 B1h = *(const uint2*)(bh1 + c2 * 8);
            uint2 B0l = *(const uint2*)(bl0 + c2 * 8);
            uint2 B1l = *(const uint2*)(bl1 + c2 * 8);
            // n-tile 0 (h 0..7)
            mma_bf16(d0[0], d0[1], d0[2], d0[3], ah0, ah1, ah2, ah3, B0h.x, B0h.y);
            mma_bf16(d0[0], d0[1], d0[2], d0[3], ah0, ah1, ah2, ah3, B0l.x, B0l.y);
            mma_bf16(d0[0], d0[1], d0[2], d0[3], al0, al1, al2, al3, B0h.x, B0h.y);
            // n-tile 1 (h 8..15)
            mma_bf16(d1[0], d1[1], d1[2], d1[3], ah0, ah1, ah2, ah3, B1h.x, B1h.y);
            mma_bf16(d1[0], d1[1], d1[2], d1[3], ah0, ah1, ah2, ah3, B1l.x, B1l.y);
            mma_bf16(d1[0], d1[1], d1[2], d1[3], al0, al1, al2, al3, B1h.x, B1h.y);
        }

        if (ch + 1 < 64) STS_CHUNK(buf ^ 1);
        __syncthreads();
    }

    // D: c0=(g,2t) c1=(g,2t+1) c2=(g+8,2t) c3=(g+8,2t+1)
    const int jA = j0 + warp * 16 + g, jB = jA + 8;
    const int hb = b * 16;
    g_scores[jA * 128 + hb + 2 * t]         = d0[0] * SCALE;
    g_scores[jA * 128 + hb + 2 * t + 1]     = d0[1] * SCALE;
    g_scores[jB * 128 + hb + 2 * t]         = d0[2] * SCALE;
    g_scores[jB * 128 + hb + 2 * t + 1]     = d0[3] * SCALE;
    g_scores[jA * 128 + hb + 8 + 2 * t]     = d1[0] * SCALE;
    g_scores[jA * 128 + hb + 8 + 2 * t + 1] = d1[1] * SCALE;
    g_scores[jB * 128 + hb + 8 + 2 * t]     = d1[2] * SCALE;
    g_scores[jB * 128 + hb + 8 + 2 * t + 1] = d1[3] * SCALE;
}

// ---------------- K3: g_scores += SCALE * (qb[b][h] . key_pos[j][h]) ----------------
__global__ __launch_bounds__(256) void k_pos(const float* __restrict__ key_pos) {
    const int warp = threadIdx.x >> 5, lane = threadIdx.x & 31;
    const int h  = blockIdx.y * 8 + warp;
    const int j0 = blockIdx.x * 4;

    u64 qb[8][2];
#pragma unroll
    for (int bb = 0; bb < 8; bb++) {
        ulonglong2 q = *(const ulonglong2*)&g_qb[bb * ND + h * NDK + lane * 4];
        qb[bb][0] = q.x; qb[bb][1] = q.y;
    }
    u64 acc[4][8];
#pragma unroll
    for (int jj = 0; jj < 4; jj++)
#pragma unroll
        for (int bb = 0; bb < 8; bb++) acc[jj][bb] = 0ull;

#pragma unroll
    for (int jj = 0; jj < 4; jj++) {
        ulonglong2 kp = *(const ulonglong2*)&key_pos[((size_t)(j0 + jj) * NH + h) * NDK + lane * 4];
#pragma unroll
        for (int bb = 0; bb < 8; bb++) {
            ffma2(acc[jj][bb], qb[bb][0], kp.x);
            ffma2(acc[jj][bb], qb[bb][1], kp.y);
        }
    }
    float v[32];
#pragma unroll
    for (int jj = 0; jj < 4; jj++)
#pragma unroll
        for (int bb = 0; bb < 8; bb++) {
            float2 p = unpack2(acc[jj][bb]);
            v[jj * 8 + bb] = p.x + p.y;
        }
    int n = 32;
#pragma unroll
    for (int half = 16; half >= 1; half >>= 1) {
        int m = n >> 1;
        bool upper = (lane & half) != 0;
#pragma unroll
        for (int i = 0; i < 16; i++) {
            if (i >= m) break;
            float send = upper ? v[i] : v[i + m];
            float recv = __shfl_xor_sync(0xffffffffu, send, half);
            v[i] = (upper ? v[i + m] : v[i]) + recv;
        }
        n = m;
    }
    int jj = lane >> 3, bb = lane & 7;
    int gi = (j0 + jj) * 128 + bb * 16 + h;
    g_scores[gi] = g_scores[gi] + v[0] * SCALE;
}

// ---------------- K5: softmax stats — block = (b, h-quad), float4 reads ----------------
__global__ __launch_bounds__(256) void k_softmax() {
    const int b = blockIdx.x >> 2, hq = blockIdx.x & 3;
    const int tid = threadIdx.x;
    const int base = b * 16 + hq * 4;
    __shared__ float red[4][256];

    float4 mx = make_float4(-1e30f, -1e30f, -1e30f, -1e30f);
    for (int j = tid; j < NS; j += 256) {
        float4 s = *(const float4*)&g_scores[j * 128 + base];
        mx.x = fmaxf(mx.x, s.x); mx.y = fmaxf(mx.y, s.y);
        mx.z = fmaxf(mx.z, s.z); mx.w = fmaxf(mx.w, s.w);
    }
    red[0][tid] = mx.x; red[1][tid] = mx.y; red[2][tid] = mx.z; red[3][tid] = mx.w;
    __syncthreads();
    for (int s = 128; s; s >>= 1) {
        if (tid < s)
#pragma unroll
            for (int q = 0; q < 4; q++)
                red[q][tid] = fmaxf(red[q][tid], red[q][tid + s]);
        __syncthreads();
    }
    float m0 = red[0][0], m1 = red[1][0], m2 = red[2][0], m3 = red[3][0];
    __syncthreads();

    float4 sum = make_float4(0.f, 0.f, 0.f, 0.f);
    for (int j = tid; j < NS; j += 256) {
        float4 s = *(const float4*)&g_scores[j * 128 + base];
        sum.x += __expf(s.x - m0); sum.y += __expf(s.y - m1);
        sum.z += __expf(s.z - m2); sum.w += __expf(s.w - m3);
    }
    red[0][tid] = sum.x; red[1][tid] = sum.y; red[2][tid] = sum.z; red[3][tid] = sum.w;
    __syncthreads();
    for (int s = 128; s; s >>= 1) {
        if (tid < s)
#pragma unroll
            for (int q = 0; q < 4; q++)
                red[q][tid] += red[q][tid + s];
        __syncthreads();
    }
    if (tid < 4) {
        float m = (tid == 0) ? m0 : (tid == 1) ? m1 : (tid == 2) ? m2 : m3;
        g_m[base + tid] = m;
        g_linv[base + tid] = 1.0f / red[tid][0];
    }
}

// ---------------- K6: value pass — float4, 4 e-cols/thread ----------------
__global__ __launch_bounds__(256) void k_value(const float* __restrict__ value) {
    const int tid = threadIdx.x;
    const int b = blockIdx.y, jc = blockIdx.z;
    const int e = blockIdx.x * 1024 + tid * 4;
    const int j0 = jc * 128;
    __shared__ __align__(16) u64 ws2[128 * 16];
    __shared__ float ms[16], ls[16];
    if (tid < 16) { ms[tid] = g_m[b * 16 + tid]; ls[tid] = g_linv[b * 16 + tid]; }
    __syncthreads();
    for (int idx = tid; idx < 2048; idx += 256) {
        int jl = idx >> 4, h = idx & 15;
        float w = __expf(g_scores[(j0 + jl) * 128 + b * 16 + h] - ms[h]) * ls[h];
        ws2[idx] = pack2(w, w);
    }
    __syncthreads();

    u64 acc[16][2];
#pragma unroll
    for (int h = 0; h < 16; h++) { acc[h][0] = 0ull; acc[h][1] = 0ull; }

    const float* vp = value + ((size_t)j0 * NB + b) * ND + e;
#pragma unroll 4
    for (int jl = 0; jl < 128; jl++) {
        ulonglong2 v2 = *(const ulonglong2*)(vp + (size_t)jl * (NB * ND));
        const ulonglong2* wr = (const ulonglong2*)(ws2 + jl * 16);
#pragma unroll
        for (int h2 = 0; h2 < 8; h2++) {
            ulonglong2 wp = wr[h2];
            ffma2(acc[2 * h2    ][0], wp.x, v2.x);
            ffma2(acc[2 * h2    ][1], wp.x, v2.y);
            ffma2(acc[2 * h2 + 1][0], wp.y, v2.x);
            ffma2(acc[2 * h2 + 1][1], wp.y, v2.y);
        }
    }
    int rb = (jc * 8 + b) * 16;
#pragma unroll
    for (int h = 0; h < 16; h++) {
        ulonglong2 o; o.x = acc[h][0]; o.y = acc[h][1];
        *(ulonglong2*)&g_upart[(size_t)(rb + h) * ND + e] = o;
    }
}

// ---------------- K7: x partials = u @ Wv (per head), e-split 16 ----------------
__global__ __launch_bounds__(128) void k_projv(const float* __restrict__ Wv) {
    int tid = threadIdx.x;   // 128 (= d)
    int h = blockIdx.y;
    int e0 = blockIdx.x * 128;
    __shared__ float us[8][128];
    for (int idx = tid; idx < 1024; idx += 128) {
        int bb = idx >> 7, el = idx & 127;
        float s = 0.f;
#pragma unroll
        for (int jc = 0; jc < 32; jc++)
            s += g_upart[(size_t)((jc * 8 + bb) * 16 + h) * ND + e0 + el];
        us[bb][el] = s;
    }
    __syncthreads();
    float acc[8] = {0.f,0.f,0.f,0.f,0.f,0.f,0.f,0.f};
    for (int el = 0; el < 128; el += 8) {
        float w[8];
#pragma unroll
        for (int k2 = 0; k2 < 8; k2++)
            w[k2] = Wv[(e0 + el + k2) * ND + h * NDK + tid];
#pragma unroll
        for (int k2 = 0; k2 < 8; k2++)
#pragma unroll
            for (int bb = 0; bb < 8; bb++) acc[bb] = fmaf(w[k2], us[bb][el + k2], acc[bb]);
    }
#pragma unroll
    for (int bb = 0; bb < 8; bb++)
        g_xpart[(blockIdx.x * 8 + bb) * ND + h * NDK + tid] = acc[bb];
}

// ---------------- K8: out partials = (xred + bv) @ Wo, xred fused into stage ----------------
__global__ __launch_bounds__(256) void k_out(const float* __restrict__ Wo,
                                             const float* __restrict__ bv) {
    int tid = threadIdx.x;
    int f = blockIdx.x * 256 + tid;
    int g0 = blockIdx.y * 128;
    __shared__ float xs[8][128];
    for (int idx = tid; idx < 1024; idx += 256) {
        int bb = idx >> 7, gl = idx & 127;
        float s = bv[g0 + gl];
#pragma unroll
        for (int ec = 0; ec < 16; ec++)
            s += g_xpart[(ec * 8 + bb) * ND + g0 + gl];
        xs[bb][gl] = s;
    }
    __syncthreads();
    float acc[8] = {0.f,0.f,0.f,0.f,0.f,0.f,0.f,0.f};
    for (int g = 0; g < 128; g += 8) {
        float w[8];
#pragma unroll
        for (int k2 = 0; k2 < 8; k2++) w[k2] = Wo[(g0 + g + k2) * ND + f];
#pragma unroll
        for (int k2 = 0; k2 < 8; k2++)
#pragma unroll
            for (int b = 0; b < 8; b++) acc[b] = fmaf(w[k2], xs[b][g + k2], acc[b]);
    }
#pragma unroll
    for (int b = 0; b < 8; b++) g_opart[(blockIdx.y * 8 + b) * ND + f] = acc[b];
}

__global__ void k_ored(const float* __restrict__ bo, float* __restrict__ out) {
    int i = blockIdx.x * 256 + threadIdx.x;
    int c = i & (ND - 1), b = i >> 11;
    float s = bo[c];
#pragma unroll
    for (int gc = 0; gc < 16; gc++) s += g_opart[(gc * 8 + b) * ND + c];
    out[i] = s;
}

extern "C" void kernel_launch(void* const* d_in, const int* in_sizes, int n_in,
                              void* d_out, int out_size) {
    const float* query   = (const float*)d_in[0];
    const float* key     = (const float*)d_in[1];
    const float* value   = (const float*)d_in[2];
    const float* Wq      = (const float*)d_in[3];
    const float* Wk      = (const float*)d_in[4];
    const float* Wv      = (const float*)d_in[5];
    const float* bv      = (const float*)d_in[6];
    const float* Wo      = (const float*)d_in[7];
    const float* bo      = (const float*)d_in[8];
    const float* key_pos = (const float*)d_in[9];
    const float* q_bias  = (const float*)d_in[10];
    float* out = (float*)d_out;

    // k_scores kept at launch idx 3 so the profiler's fixed slot lands on it.
    k_qbp    <<<dim3(8, 16),     256>>>(query, Wq);
    k_qb     <<<64,              256>>>(q_bias);
    k_A      <<<dim3(16, 16),    128>>>(Wk);
    k_scores <<<dim3(64, 8),     128>>>(key);
    k_pos    <<<dim3(1024, 2),   256>>>(key_pos);
    k_softmax<<<32,              256>>>();
    k_value  <<<dim3(2, 8, 32),  256>>>(value);
    k_projv  <<<dim3(16, 16),    128>>>(Wv);
    k_out    <<<dim3(8, 16),     256>>>(Wo, bv);
    k_ored   <<<64,              256>>>(bo, out);
}